// round 3
// baseline (speedup 1.0000x reference)
#include <cuda_runtime.h>
#include <cstdint>

#define HID 512
#define BAT 32
#define TLEN 512
#define G4 2048
#define NBLK 128
#define WP 68    // ht/Wt kp-row pitch (64 data + 4 pad)
#define RP 36    // red row pitch (conflict-free for rg*8+bg*2 pattern)

// ----------------------------------------------------------------------------
// Scratch (static __device__ — no allocations allowed)
// ----------------------------------------------------------------------------
__device__ float    g_xg[2][TLEN][BAT][G4];     // xg[dir][t][b][gate]
__device__ float    g_hpkt[2][2][64][256];      // [parity][dir][prod][kp-packed 4x64]
__device__ unsigned g_seq[2][2][64];            // [parity][dir][prod] = s+1 when published

// ----------------------------------------------------------------------------
// helpers
// ----------------------------------------------------------------------------
__device__ __forceinline__ void ffma2(unsigned long long& d,
                                      unsigned long long a,
                                      unsigned long long b)
{
    asm("fma.rn.f32x2 %0, %1, %2, %0;" : "+l"(d) : "l"(a), "l"(b));
}
__device__ __forceinline__ float lo32(unsigned long long v)
{ return __uint_as_float((unsigned)(v & 0xffffffffull)); }
__device__ __forceinline__ float hi32(unsigned long long v)
{ return __uint_as_float((unsigned)(v >> 32)); }

__device__ __forceinline__ float fex2(float x)
{ float y; asm("ex2.approx.f32 %0, %1;" : "=f"(y) : "f"(x)); return y; }
__device__ __forceinline__ float frcp(float x)
{ float y; asm("rcp.approx.f32 %0, %1;" : "=f"(y) : "f"(x)); return y; }

__device__ __forceinline__ float fsigmoid(float x)
{   // 1/(1+2^(-x*log2e))
    return frcp(1.f + fex2(-1.4426950408889634f * x));
}
__device__ __forceinline__ float ftanh(float x)
{   // 1 - 2e/(1+e), e = 2^(-2|x|*log2e)
    float ax = fabsf(x);
    float e = fex2(-2.8853900817779268f * ax);
    float t = 1.f - 2.f * e * frcp(1.f + e);
    return copysignf(t, x);
}

__device__ __forceinline__ void st_release(unsigned* p, unsigned v)
{ asm volatile("st.release.gpu.u32 [%0], %1;" :: "l"(p), "r"(v) : "memory"); }
__device__ __forceinline__ unsigned ld_acquire(const unsigned* p)
{ unsigned v; asm volatile("ld.acquire.gpu.u32 %0, [%1];" : "=r"(v) : "l"(p) : "memory"); return v; }

// ----------------------------------------------------------------------------
// Kernel 0: reset publish sequence words (stream-ordered before scan)
// ----------------------------------------------------------------------------
__global__ void reset_seq_kernel()
{
    ((unsigned*)g_seq)[threadIdx.x] = 0u;
}

// ----------------------------------------------------------------------------
// Kernel 1: xg = x @ Wih^T + bih + bhh, both dirs (blockIdx.z).
// 128x128x16 tiled SGEMM; B-operand uses split-column tiles (tx*4, 64+tx*4)
// so quarter-warp LDS.128 addresses cover 32 distinct banks (conflict-free).
// ----------------------------------------------------------------------------
__global__ void __launch_bounds__(256) gemm_xg_kernel(
    const float* __restrict__ A,
    const float* __restrict__ Wf, const float* __restrict__ Wb,
    const float* __restrict__ bihf, const float* __restrict__ bhhf,
    const float* __restrict__ bihb, const float* __restrict__ bhhb)
{
    __shared__ float As[16][132];
    __shared__ float Bs[16][132];

    const int dir = blockIdx.z;
    const float* __restrict__ W   = dir ? Wb : Wf;
    const float* __restrict__ bih = dir ? bihb : bihf;
    const float* __restrict__ bhh = dir ? bhhb : bhhf;

    const int m0 = blockIdx.y * 128;
    const int n0 = blockIdx.x * 128;
    const int tid = threadIdx.x;
    const int tx = tid & 15;
    const int ty = tid >> 4;
    const int lrow = tid >> 2;
    const int lkc  = (tid & 3) * 4;

    float acc[8][8];
    #pragma unroll
    for (int i = 0; i < 8; i++)
        #pragma unroll
        for (int j = 0; j < 8; j++) acc[i][j] = 0.f;

    for (int k0 = 0; k0 < 512; k0 += 16) {
        #pragma unroll
        for (int u = 0; u < 2; u++) {
            int row = lrow + u * 64;
            float4 av = *(const float4*)&A[(size_t)(m0 + row) * 512 + k0 + lkc];
            As[lkc + 0][row] = av.x; As[lkc + 1][row] = av.y;
            As[lkc + 2][row] = av.z; As[lkc + 3][row] = av.w;
            float4 bv = *(const float4*)&W[(size_t)(n0 + row) * 512 + k0 + lkc];
            Bs[lkc + 0][row] = bv.x; Bs[lkc + 1][row] = bv.y;
            Bs[lkc + 2][row] = bv.z; Bs[lkc + 3][row] = bv.w;
        }
        __syncthreads();
        #pragma unroll
        for (int k = 0; k < 16; k++) {
            float a[8], b[8];
            *(float4*)&a[0] = *(const float4*)&As[k][ty * 8];
            *(float4*)&a[4] = *(const float4*)&As[k][ty * 8 + 4];
            *(float4*)&b[0] = *(const float4*)&Bs[k][tx * 4];        // cols n0+tx*4+0..3
            *(float4*)&b[4] = *(const float4*)&Bs[k][64 + tx * 4];   // cols n0+64+tx*4+0..3
            #pragma unroll
            for (int i = 0; i < 8; i++)
                #pragma unroll
                for (int j = 0; j < 8; j++)
                    acc[i][j] = fmaf(a[i], b[j], acc[i][j]);
        }
        __syncthreads();
    }

    float bias[8];
    #pragma unroll
    for (int j = 0; j < 4; j++) {
        int n = n0 + tx * 4 + j;
        bias[j]     = bih[n]      + bhh[n];
        bias[4 + j] = bih[n + 64] + bhh[n + 64];
    }
    #pragma unroll
    for (int i = 0; i < 8; i++) {
        int m = m0 + ty * 8 + i;
        int t = m & 511;
        int b = m >> 9;
        float* o = &g_xg[dir][t][b][n0];
        float4 v0 = make_float4(acc[i][0] + bias[0], acc[i][1] + bias[1],
                                acc[i][2] + bias[2], acc[i][3] + bias[3]);
        float4 v1 = make_float4(acc[i][4] + bias[4], acc[i][5] + bias[5],
                                acc[i][6] + bias[6], acc[i][7] + bias[7]);
        *(float4*)&o[tx * 4]      = v0;
        *(float4*)&o[64 + tx * 4] = v1;
    }
}

// ----------------------------------------------------------------------------
// Kernel 2: persistent scan with dataflow h-exchange (no central barrier).
// 128 blocks: dir = blk>>6, prod = blk&63 owns hidden units j0..j0+7.
// smem (k-pair packed for f32x2):
//   Wt[kp][r*2+p], r = gate*8+jj  (Whh slice, transposed)
//   ht[kp][b*2+p]                 (previous h, all 512 k)
//   red[warp][ri][bj], pitch RP   (cross-k partials)
// Matmul: ks=tid>>4 (16-way k-split), rg=(tid>>2)&3, bg=tid&3;
//   split-pair tiles: rows {j*8+rg*2+p}, batches {j*8+bg*2+p} — LDS conflict-free.
// Publish: pkt rows are ht-row fragments -> consumer copy is 16x float4, no transpose.
// ----------------------------------------------------------------------------
#define SMEM_FLOATS (2 * 256 * WP + 8 * 32 * RP)   // 44032 floats = 176128 B

__global__ void __launch_bounds__(256, 1) lstm_scan_kernel(
    const float* __restrict__ Whh_f,
    const float* __restrict__ Whh_b,
    float* __restrict__ out)
{
    extern __shared__ float sm[];
    float* Wt  = sm;                        // [256][WP]
    float* ht  = sm + 256 * WP;             // [256][WP]
    float* red = sm + 2 * 256 * WP;         // [8][32][RP]

    const int tid  = threadIdx.x;
    const int dir  = blockIdx.x >> 6;
    const int prod = blockIdx.x & 63;
    const int j0   = prod * 8;
    const float* __restrict__ Whh = dir ? Whh_b : Whh_f;

    // prologue: Wt[kp][r*2+p] from Whh rows gate*512 + j0 + jj
    {
        int r  = tid & 31;
        int gr = (r >> 3) * 512 + j0 + (r & 7);
        const float* src = Whh + (size_t)gr * 512;
        int k0 = (tid >> 5) * 64;
        for (int k = k0; k < k0 + 64; k += 4) {
            float4 v = *(const float4*)&src[k];
            int kp = k >> 1;
            Wt[kp * WP + r * 2 + 0]       = v.x;
            Wt[kp * WP + r * 2 + 1]       = v.y;
            Wt[(kp + 1) * WP + r * 2 + 0] = v.z;
            Wt[(kp + 1) * WP + r * 2 + 1] = v.w;
        }
    }
    for (int i = tid; i < 256 * WP; i += 256) ht[i] = 0.f;

    const int ks   = tid >> 4;     // 0..15 k-slice
    const int rg   = (tid >> 2) & 3;
    const int bg   = tid & 3;
    const int warp = tid >> 5;
    const int fb   = tid >> 3;     // finalize batch
    const int fj   = tid & 7;      // finalize hidden unit
    const int cp_p = tid >> 2;     // consumer: producer index
    const int cp_q = tid & 3;      // consumer: quarter of packet
    float c_state = 0.f;

    const float* xg_base = &g_xg[dir][0][fb][j0 + fj];
    float* out_base = out + (size_t)fb * (TLEN * 1024) + dir * 512 + j0 + fj;
    const int myoff = (fj >> 1) * 64 + fb * 2 + (fj & 1);   // pkt offset (kp-packed)

    __syncthreads();

    for (int s = 0; s < 512; s++) {
        const int t = dir ? (511 - s) : s;

        // prefetch xg for this thread's cell
        const float* xgp = xg_base + (size_t)t * (BAT * G4);
        float xi  = xgp[0];
        float xf  = xgp[512];
        float xgv = xgp[1024];
        float xo  = xgp[1536];

        // ---- matmul, k-pair packed, conflict-free split-pair tiles
        unsigned long long acc2[8][8];
        #pragma unroll
        for (int i = 0; i < 8; i++)
            #pragma unroll
            for (int j = 0; j < 8; j++) acc2[i][j] = 0ull;

        #pragma unroll 4
        for (int kk = 0; kk < 16; kk++) {
            const float* base = sm + (kk * 16 + ks) * WP;           // Wt row
            const float* hbase = base + 256 * WP;                   // ht row
            unsigned long long a2[8], h2[8];
            #pragma unroll
            for (int j = 0; j < 4; j++) {
                ulonglong2 va = *(const ulonglong2*)(base + j * 16 + rg * 4);
                a2[2 * j] = va.x; a2[2 * j + 1] = va.y;
                ulonglong2 vh = *(const ulonglong2*)(hbase + j * 16 + bg * 4);
                h2[2 * j] = vh.x; h2[2 * j + 1] = vh.y;
            }
            #pragma unroll
            for (int i = 0; i < 8; i++)
                #pragma unroll
                for (int j = 0; j < 8; j++)
                    ffma2(acc2[i][j], a2[i], h2[j]);
        }

        // fold packed halves + k-slice pairs (lane^16)
        float accs[8][8];
        #pragma unroll
        for (int i = 0; i < 8; i++)
            #pragma unroll
            for (int j = 0; j < 8; j++) {
                float v = lo32(acc2[i][j]) + hi32(acc2[i][j]);
                accs[i][j] = v + __shfl_xor_sync(0xffffffffu, v, 16);
            }

        if ((tid & 16) == 0) {
            #pragma unroll
            for (int i = 0; i < 8; i++) {
                int ri = (i >> 1) * 8 + rg * 2 + (i & 1);
                float* rp = red + warp * (32 * RP) + ri * RP + bg * 2;
                *(float2*)&rp[0]  = make_float2(accs[i][0], accs[i][1]);
                *(float2*)&rp[8]  = make_float2(accs[i][2], accs[i][3]);
                *(float2*)&rp[16] = make_float2(accs[i][4], accs[i][5]);
                *(float2*)&rp[24] = make_float2(accs[i][6], accs[i][7]);
            }
        }
        __syncthreads();

        // ---- finalize (b=fb, j=j0+fj); red rows: gate*8+fj
        {
            float d0 = 0.f, d1 = 0.f, d2 = 0.f, d3 = 0.f;
            #pragma unroll
            for (int w = 0; w < 8; w++) {
                const float* rp = red + w * (32 * RP) + fj * RP + fb;
                d0 += rp[0];
                d1 += rp[8 * RP];
                d2 += rp[16 * RP];
                d3 += rp[24 * RP];
            }
            float ig = fsigmoid(xi + d0);
            float fg = fsigmoid(xf + d1);
            float gg = ftanh(xgv + d2);
            float og = fsigmoid(xo + d3);
            c_state = fg * c_state + ig * gg;
            float hval = og * ftanh(c_state);

            out_base[(size_t)t * 1024] = hval;
            if (s < 511)
                g_hpkt[s & 1][dir][prod][myoff] = hval;
        }
        __syncthreads();

        if (s < 511) {
            // publish (release) — pkt writes of all threads ordered via bar + cumulativity
            if (tid == 0)
                st_release(&g_seq[s & 1][dir][prod], (unsigned)(s + 1));

            // consume: thread owns producer cp_p, quarter cp_q; dst row = tid
            const unsigned want = (unsigned)(s + 1);
            const unsigned* sq = &g_seq[s & 1][dir][cp_p];
            while (ld_acquire(sq) != want) { }
            const float4* src = (const float4*)&g_hpkt[s & 1][dir][cp_p][cp_q * 64];
            float4* dst = (float4*)&ht[tid * WP];
            #pragma unroll
            for (int c = 0; c < 16; c++) dst[c] = src[c];
            __syncthreads();
        }
    }
}

// ----------------------------------------------------------------------------
// Launch
// ----------------------------------------------------------------------------
extern "C" void kernel_launch(void* const* d_in, const int* in_sizes, int n_in,
                              void* d_out, int out_size)
{
    (void)in_sizes; (void)n_in; (void)out_size;
    const float* x     = (const float*)d_in[0];
    const float* Wih_f = (const float*)d_in[1];
    const float* Whh_f = (const float*)d_in[2];
    const float* bih_f = (const float*)d_in[3];
    const float* bhh_f = (const float*)d_in[4];
    const float* Wih_b = (const float*)d_in[5];
    const float* Whh_b = (const float*)d_in[6];
    const float* bih_b = (const float*)d_in[7];
    const float* bhh_b = (const float*)d_in[8];
    float* out = (float*)d_out;

    static bool attr_set = false;
    if (!attr_set) {
        cudaFuncSetAttribute(lstm_scan_kernel,
                             cudaFuncAttributeMaxDynamicSharedMemorySize,
                             SMEM_FLOATS * (int)sizeof(float));
        attr_set = true;
    }

    reset_seq_kernel<<<1, 256>>>();
    dim3 ggrid(16, 128, 2);
    gemm_xg_kernel<<<ggrid, 256>>>(x, Wih_f, Wih_b, bih_f, bhh_f, bih_b, bhh_b);
    lstm_scan_kernel<<<NBLK, 256, SMEM_FLOATS * sizeof(float)>>>(Whh_f, Whh_b, out);
}

// round 4
// speedup vs baseline: 1.1519x; 1.1519x over previous
#include <cuda_runtime.h>
#include <cstdint>

#define HID 512
#define BAT 32
#define TLEN 512
#define G4 2048
#define NBLK 128
#define NBLK_DIR 64
#define WP 80    // kp-row pitch: 80 % 32 == 16 -> ks half-warps use complementary banks
#define RP 36    // red row pitch

// ----------------------------------------------------------------------------
// Scratch (static __device__ — no allocations allowed)
// ----------------------------------------------------------------------------
__device__ float    g_xg[2][TLEN][BAT][G4];    // xg[dir][t][b][gate]
__device__ float    g_hbuf[2][2][BAT][HID];    // [parity][dir][b][j]
__device__ unsigned g_bar_cnt[2][32];          // [dir][0], 128B-separated
__device__ volatile unsigned g_bar_gen[2][32];

// ----------------------------------------------------------------------------
// helpers
// ----------------------------------------------------------------------------
__device__ __forceinline__ void ffma2(unsigned long long& d,
                                      unsigned long long a,
                                      unsigned long long b)
{
    asm("fma.rn.f32x2 %0, %1, %2, %0;" : "+l"(d) : "l"(a), "l"(b));
}
__device__ __forceinline__ float lo32(unsigned long long v)
{ return __uint_as_float((unsigned)(v & 0xffffffffull)); }
__device__ __forceinline__ float hi32(unsigned long long v)
{ return __uint_as_float((unsigned)(v >> 32)); }

__device__ __forceinline__ float fex2(float x)
{ float y; asm("ex2.approx.f32 %0, %1;" : "=f"(y) : "f"(x)); return y; }
__device__ __forceinline__ float frcp(float x)
{ float y; asm("rcp.approx.f32 %0, %1;" : "=f"(y) : "f"(x)); return y; }

__device__ __forceinline__ float fsigmoid(float x)
{ return frcp(1.f + fex2(-1.4426950408889634f * x)); }
__device__ __forceinline__ float ftanh(float x)
{
    float ax = fabsf(x);
    float e = fex2(-2.8853900817779268f * ax);
    float t = 1.f - 2.f * e * frcp(1.f + e);
    return copysignf(t, x);
}

// ----------------------------------------------------------------------------
// Kernel 1: xg = x @ Wih^T + bih + bhh, both dirs via blockIdx.z.
// 128x128x16 tiled SGEMM; B-operand split-column tiles (tx*4, 64+tx*4):
// quarter-warp LDS.128 covers 32 distinct banks (conflict-free).
// ----------------------------------------------------------------------------
__global__ void __launch_bounds__(256) gemm_xg_kernel(
    const float* __restrict__ A,
    const float* __restrict__ Wf, const float* __restrict__ Wb,
    const float* __restrict__ bihf, const float* __restrict__ bhhf,
    const float* __restrict__ bihb, const float* __restrict__ bhhb)
{
    __shared__ float As[16][132];
    __shared__ float Bs[16][132];

    const int dir = blockIdx.z;
    const float* __restrict__ W   = dir ? Wb : Wf;
    const float* __restrict__ bih = dir ? bihb : bihf;
    const float* __restrict__ bhh = dir ? bhhb : bhhf;

    const int m0 = blockIdx.y * 128;
    const int n0 = blockIdx.x * 128;
    const int tid = threadIdx.x;
    const int tx = tid & 15;
    const int ty = tid >> 4;
    const int lrow = tid >> 2;
    const int lkc  = (tid & 3) * 4;

    float acc[8][8];
    #pragma unroll
    for (int i = 0; i < 8; i++)
        #pragma unroll
        for (int j = 0; j < 8; j++) acc[i][j] = 0.f;

    for (int k0 = 0; k0 < 512; k0 += 16) {
        #pragma unroll
        for (int u = 0; u < 2; u++) {
            int row = lrow + u * 64;
            float4 av = *(const float4*)&A[(size_t)(m0 + row) * 512 + k0 + lkc];
            As[lkc + 0][row] = av.x; As[lkc + 1][row] = av.y;
            As[lkc + 2][row] = av.z; As[lkc + 3][row] = av.w;
            float4 bv = *(const float4*)&W[(size_t)(n0 + row) * 512 + k0 + lkc];
            Bs[lkc + 0][row] = bv.x; Bs[lkc + 1][row] = bv.y;
            Bs[lkc + 2][row] = bv.z; Bs[lkc + 3][row] = bv.w;
        }
        __syncthreads();
        #pragma unroll
        for (int k = 0; k < 16; k++) {
            float a[8], b[8];
            *(float4*)&a[0] = *(const float4*)&As[k][ty * 8];
            *(float4*)&a[4] = *(const float4*)&As[k][ty * 8 + 4];
            *(float4*)&b[0] = *(const float4*)&Bs[k][tx * 4];
            *(float4*)&b[4] = *(const float4*)&Bs[k][64 + tx * 4];
            #pragma unroll
            for (int i = 0; i < 8; i++)
                #pragma unroll
                for (int j = 0; j < 8; j++)
                    acc[i][j] = fmaf(a[i], b[j], acc[i][j]);
        }
        __syncthreads();
    }

    float bias[8];
    #pragma unroll
    for (int j = 0; j < 4; j++) {
        int n = n0 + tx * 4 + j;
        bias[j]     = bih[n]      + bhh[n];
        bias[4 + j] = bih[n + 64] + bhh[n + 64];
    }
    #pragma unroll
    for (int i = 0; i < 8; i++) {
        int m = m0 + ty * 8 + i;
        int t = m & 511;
        int b = m >> 9;
        float* o = &g_xg[dir][t][b][n0];
        float4 v0 = make_float4(acc[i][0] + bias[0], acc[i][1] + bias[1],
                                acc[i][2] + bias[2], acc[i][3] + bias[3]);
        float4 v1 = make_float4(acc[i][4] + bias[4], acc[i][5] + bias[5],
                                acc[i][6] + bias[6], acc[i][7] + bias[7]);
        *(float4*)&o[tx * 4]      = v0;
        *(float4*)&o[64 + tx * 4] = v1;
    }
}

// ----------------------------------------------------------------------------
// Per-direction graph-replay-safe generation barrier (64 co-resident blocks).
// ----------------------------------------------------------------------------
__device__ __forceinline__ void grid_barrier(int dir)
{
    __threadfence();
    __syncthreads();
    if (threadIdx.x == 0) {
        unsigned* cnt = &g_bar_cnt[dir][0];
        volatile unsigned* gen = &g_bar_gen[dir][0];
        unsigned g = *gen;
        unsigned ticket = atomicAdd(cnt, 1u);
        if (ticket == NBLK_DIR - 1u) {
            *cnt = 0u;
            __threadfence();
            *gen = g + 1u;
        } else {
            while (*gen == g) { }
        }
        __threadfence();
    }
    __syncthreads();
}

// ----------------------------------------------------------------------------
// Kernel 2: persistent scan. 128 blocks: dir = blk>>6, slice of 8 hidden units.
// smem (k-pair packed, f32x2):
//   Wt[kp][r*2+p]  r = gate*8+jj   pitch WP=80  (80%32==16 -> bank-split halves)
//   ht[kp][b*2+p]                  pitch WP
//   red[warp][row][col]            pitch RP=36
// Matmul map: ks = tid>>4 (16 k-slices, half-warp pairs folded by shfl^16),
//   rg=(tid>>2)&3, bg=tid&3; split-pair tiles:
//   rows r(i) = (i>>1)*8 + rg*2 + (i&1), batches b(j) = (j>>1)*8 + bg*2 + (j&1).
// All hot LDS/STS verified conflict-free (32 distinct banks per phase).
// ----------------------------------------------------------------------------
#define SMEM_FLOATS (2 * 256 * WP + 8 * 32 * RP)   // 50176 floats = 200704 B

__global__ void __launch_bounds__(256, 1) lstm_scan_kernel(
    const float* __restrict__ Whh_f,
    const float* __restrict__ Whh_b,
    float* __restrict__ out)
{
    extern __shared__ float sm[];
    float* Wt  = sm;                        // [256][WP]
    float* ht  = sm + 256 * WP;             // [256][WP]
    float* red = sm + 2 * 256 * WP;         // [8][32][RP]

    const int tid = threadIdx.x;
    const int dir = blockIdx.x >> 6;
    const int j0  = (blockIdx.x & 63) * 8;
    const float* __restrict__ Whh = dir ? Whh_b : Whh_f;

    // prologue: Wt[kp][r*2+p] from Whh rows gate*512 + j0 + jj
    {
        int r  = tid & 31;
        int gr = (r >> 3) * 512 + j0 + (r & 7);
        const float* src = Whh + (size_t)gr * 512;
        int k0 = (tid >> 5) * 64;
        for (int k = k0; k < k0 + 64; k += 4) {
            float4 v = *(const float4*)&src[k];
            int kp = k >> 1;
            Wt[kp * WP + r * 2 + 0]       = v.x;
            Wt[kp * WP + r * 2 + 1]       = v.y;
            Wt[(kp + 1) * WP + r * 2 + 0] = v.z;
            Wt[(kp + 1) * WP + r * 2 + 1] = v.w;
        }
    }
    for (int i = tid; i < 256 * WP; i += 256) ht[i] = 0.f;

    const int ks   = tid >> 4;
    const int rg   = (tid >> 2) & 3;
    const int bg   = tid & 3;
    const int warp = tid >> 5;
    const int fb   = tid >> 3;     // finalize batch
    const int fj   = tid & 7;      // finalize hidden unit
    float c_state = 0.f;

    const float* xg_base = &g_xg[dir][0][fb][j0 + fj];
    float* out_base = out + (size_t)fb * (TLEN * 1024) + dir * 512 + j0 + fj;
    float* hb0 = &g_hbuf[0][dir][fb][j0 + fj];
    float* hb1 = &g_hbuf[1][dir][fb][j0 + fj];

    __syncthreads();

    for (int s = 0; s < 512; s++) {
        const int t = dir ? (511 - s) : s;

        // prefetch xg (hidden under matmul)
        const float* xgp = xg_base + (size_t)t * (BAT * G4);
        float xi  = xgp[0];
        float xf  = xgp[512];
        float xgv = xgp[1024];
        float xo  = xgp[1536];

        // ---- matmul (f32x2, conflict-free)
        unsigned long long acc2[8][8];
        #pragma unroll
        for (int i = 0; i < 8; i++)
            #pragma unroll
            for (int j = 0; j < 8; j++) acc2[i][j] = 0ull;

        #pragma unroll 4
        for (int kk = 0; kk < 16; kk++) {
            const float* wrow = Wt + (kk * 16 + ks) * WP;
            const float* hrow = wrow + 256 * WP;
            unsigned long long a2[8], h2[8];
            #pragma unroll
            for (int j = 0; j < 4; j++) {
                ulonglong2 va = *(const ulonglong2*)(wrow + j * 16 + rg * 4);
                a2[2 * j] = va.x; a2[2 * j + 1] = va.y;
                ulonglong2 vh = *(const ulonglong2*)(hrow + j * 16 + bg * 4);
                h2[2 * j] = vh.x; h2[2 * j + 1] = vh.y;
            }
            #pragma unroll
            for (int i = 0; i < 8; i++)
                #pragma unroll
                for (int j = 0; j < 8; j++)
                    ffma2(acc2[i][j], a2[i], h2[j]);
        }

        // fold packed halves + ks pairs (lane^16: same rg/bg, ks^1)
        float accs[8][8];
        #pragma unroll
        for (int i = 0; i < 8; i++)
            #pragma unroll
            for (int j = 0; j < 8; j++) {
                float v = lo32(acc2[i][j]) + hi32(acc2[i][j]);
                accs[i][j] = v + __shfl_xor_sync(0xffffffffu, v, 16);
            }

        if ((tid & 16) == 0) {
            #pragma unroll
            for (int i = 0; i < 8; i++) {
                int r = ((i >> 1) * 8) + rg * 2 + (i & 1);
                float* rp = red + warp * (32 * RP) + r * RP + bg * 2;
                *(float2*)&rp[0]  = make_float2(accs[i][0], accs[i][1]);
                *(float2*)&rp[8]  = make_float2(accs[i][2], accs[i][3]);
                *(float2*)&rp[16] = make_float2(accs[i][4], accs[i][5]);
                *(float2*)&rp[24] = make_float2(accs[i][6], accs[i][7]);
            }
        }
        __syncthreads();

        // ---- finalize: thread (fb, fj); gate rows g*8+fj, column fb
        {
            float d0 = 0.f, d1 = 0.f, d2 = 0.f, d3 = 0.f;
            #pragma unroll
            for (int w = 0; w < 8; w++) {
                const float* rp = red + w * (32 * RP) + fj * RP + fb;
                d0 += rp[0];
                d1 += rp[8 * RP];
                d2 += rp[16 * RP];
                d3 += rp[24 * RP];
            }
            float ig = fsigmoid(xi + d0);
            float fg = fsigmoid(xf + d1);
            float gg = ftanh(xgv + d2);
            float og = fsigmoid(xo + d3);
            c_state = fg * c_state + ig * gg;
            float hval = og * ftanh(c_state);

            out_base[(size_t)t * 1024] = hval;
            if (s < 511)
                *((s & 1) ? hb1 : hb0) = hval;
        }

        if (s < 511) {
            grid_barrier(dir);
            // reload full h (transpose + k-pair pack)
            int b  = tid & 31;
            int k0 = (tid >> 5) * 64;
            const float* src = &g_hbuf[s & 1][dir][b][0];
            for (int k = k0; k < k0 + 64; k += 4) {
                float4 v = *(const float4*)&src[k];
                int kp = k >> 1;
                *(float2*)&ht[kp * WP + b * 2]       = make_float2(v.x, v.y);
                *(float2*)&ht[(kp + 1) * WP + b * 2] = make_float2(v.z, v.w);
            }
            __syncthreads();
        }
    }
}

// ----------------------------------------------------------------------------
// Launch
// ----------------------------------------------------------------------------
extern "C" void kernel_launch(void* const* d_in, const int* in_sizes, int n_in,
                              void* d_out, int out_size)
{
    (void)in_sizes; (void)n_in; (void)out_size;
    const float* x     = (const float*)d_in[0];
    const float* Wih_f = (const float*)d_in[1];
    const float* Whh_f = (const float*)d_in[2];
    const float* bih_f = (const float*)d_in[3];
    const float* bhh_f = (const float*)d_in[4];
    const float* Wih_b = (const float*)d_in[5];
    const float* Whh_b = (const float*)d_in[6];
    const float* bih_b = (const float*)d_in[7];
    const float* bhh_b = (const float*)d_in[8];
    float* out = (float*)d_out;

    static bool attr_set = false;
    if (!attr_set) {
        cudaFuncSetAttribute(lstm_scan_kernel,
                             cudaFuncAttributeMaxDynamicSharedMemorySize,
                             SMEM_FLOATS * (int)sizeof(float));
        attr_set = true;
    }

    dim3 ggrid(16, 128, 2);
    gemm_xg_kernel<<<ggrid, 256>>>(x, Wih_f, Wih_b, bih_f, bhh_f, bih_b, bhh_b);
    lstm_scan_kernel<<<NBLK, 256, SMEM_FLOATS * sizeof(float)>>>(Whh_f, Whh_b, out);
}

// round 5
// speedup vs baseline: 1.2019x; 1.0434x over previous
#include <cuda_runtime.h>
#include <cstdint>

#define HID 512
#define BAT 32
#define TLEN 512
#define G4 2048
#define NBLK 128
#define NBLK_DIR 64
#define WP 64    // kp-row pitch (no pad needed: all hot accesses are same-row)
#define RP 36    // red row pitch (finalize reads conflict-free)

// ----------------------------------------------------------------------------
// Scratch (static __device__ — no allocations allowed)
// ----------------------------------------------------------------------------
__device__ float    g_xg[2][TLEN][BAT][G4];    // xg[dir][t][b][gate]
__device__ float    g_hbuf[2][2][BAT][HID];    // [parity][dir][b][j]
__device__ unsigned g_cnt[2][32];              // [dir][0] monotonic arrival counter

// ----------------------------------------------------------------------------
// helpers
// ----------------------------------------------------------------------------
__device__ __forceinline__ void ffma2(unsigned long long& d,
                                      unsigned long long a,
                                      unsigned long long b)
{
    asm("fma.rn.f32x2 %0, %1, %2, %0;" : "+l"(d) : "l"(a), "l"(b));
}
__device__ __forceinline__ float lo32(unsigned long long v)
{ return __uint_as_float((unsigned)(v & 0xffffffffull)); }
__device__ __forceinline__ float hi32(unsigned long long v)
{ return __uint_as_float((unsigned)(v >> 32)); }

__device__ __forceinline__ float fex2(float x)
{ float y; asm("ex2.approx.f32 %0, %1;" : "=f"(y) : "f"(x)); return y; }
__device__ __forceinline__ float frcp(float x)
{ float y; asm("rcp.approx.f32 %0, %1;" : "=f"(y) : "f"(x)); return y; }

__device__ __forceinline__ float fsigmoid(float x)
{ return frcp(1.f + fex2(-1.4426950408889634f * x)); }
__device__ __forceinline__ float ftanh(float x)
{
    float ax = fabsf(x);
    float e = fex2(-2.8853900817779268f * ax);
    float t = 1.f - 2.f * e * frcp(1.f + e);
    return copysignf(t, x);
}

__device__ __forceinline__ void red_add_release(unsigned* p)
{ asm volatile("red.release.gpu.global.add.u32 [%0], 1;" :: "l"(p) : "memory"); }
__device__ __forceinline__ unsigned ld_acquire(const unsigned* p)
{ unsigned v; asm volatile("ld.acquire.gpu.global.u32 %0, [%1];" : "=r"(v) : "l"(p) : "memory"); return v; }

// ----------------------------------------------------------------------------
// Kernel 0: zero arrival counters (stream-ordered before scan, replay-safe)
// ----------------------------------------------------------------------------
__global__ void reset_cnt_kernel()
{
    ((unsigned*)g_cnt)[threadIdx.x] = 0u;
}

// ----------------------------------------------------------------------------
// Kernel 1: xg = x @ Wih^T + bih + bhh, both dirs via blockIdx.z.
// 128x128x16 tiled SGEMM; conflict-free B reads via split-column tiles.
// ----------------------------------------------------------------------------
__global__ void __launch_bounds__(256) gemm_xg_kernel(
    const float* __restrict__ A,
    const float* __restrict__ Wf, const float* __restrict__ Wb,
    const float* __restrict__ bihf, const float* __restrict__ bhhf,
    const float* __restrict__ bihb, const float* __restrict__ bhhb)
{
    __shared__ float As[16][132];
    __shared__ float Bs[16][132];

    const int dir = blockIdx.z;
    const float* __restrict__ W   = dir ? Wb : Wf;
    const float* __restrict__ bih = dir ? bihb : bihf;
    const float* __restrict__ bhh = dir ? bhhb : bhhf;

    const int m0 = blockIdx.y * 128;
    const int n0 = blockIdx.x * 128;
    const int tid = threadIdx.x;
    const int tx = tid & 15;
    const int ty = tid >> 4;
    const int lrow = tid >> 2;
    const int lkc  = (tid & 3) * 4;

    float acc[8][8];
    #pragma unroll
    for (int i = 0; i < 8; i++)
        #pragma unroll
        for (int j = 0; j < 8; j++) acc[i][j] = 0.f;

    for (int k0 = 0; k0 < 512; k0 += 16) {
        #pragma unroll
        for (int u = 0; u < 2; u++) {
            int row = lrow + u * 64;
            float4 av = *(const float4*)&A[(size_t)(m0 + row) * 512 + k0 + lkc];
            As[lkc + 0][row] = av.x; As[lkc + 1][row] = av.y;
            As[lkc + 2][row] = av.z; As[lkc + 3][row] = av.w;
            float4 bv = *(const float4*)&W[(size_t)(n0 + row) * 512 + k0 + lkc];
            Bs[lkc + 0][row] = bv.x; Bs[lkc + 1][row] = bv.y;
            Bs[lkc + 2][row] = bv.z; Bs[lkc + 3][row] = bv.w;
        }
        __syncthreads();
        #pragma unroll
        for (int k = 0; k < 16; k++) {
            float a[8], b[8];
            *(float4*)&a[0] = *(const float4*)&As[k][ty * 8];
            *(float4*)&a[4] = *(const float4*)&As[k][ty * 8 + 4];
            *(float4*)&b[0] = *(const float4*)&Bs[k][tx * 4];
            *(float4*)&b[4] = *(const float4*)&Bs[k][64 + tx * 4];
            #pragma unroll
            for (int i = 0; i < 8; i++)
                #pragma unroll
                for (int j = 0; j < 8; j++)
                    acc[i][j] = fmaf(a[i], b[j], acc[i][j]);
        }
        __syncthreads();
    }

    float bias[8];
    #pragma unroll
    for (int j = 0; j < 4; j++) {
        int n = n0 + tx * 4 + j;
        bias[j]     = bih[n]      + bhh[n];
        bias[4 + j] = bih[n + 64] + bhh[n + 64];
    }
    #pragma unroll
    for (int i = 0; i < 8; i++) {
        int m = m0 + ty * 8 + i;
        int t = m & 511;
        int b = m >> 9;
        float* o = &g_xg[dir][t][b][n0];
        float4 v0 = make_float4(acc[i][0] + bias[0], acc[i][1] + bias[1],
                                acc[i][2] + bias[2], acc[i][3] + bias[3]);
        float4 v1 = make_float4(acc[i][4] + bias[4], acc[i][5] + bias[5],
                                acc[i][6] + bias[6], acc[i][7] + bias[7]);
        *(float4*)&o[tx * 4]      = v0;
        *(float4*)&o[64 + tx * 4] = v1;
    }
}

// ----------------------------------------------------------------------------
// Kernel 2: persistent scan. 128 blocks: dir = blk>>6, 8 hidden units each.
// smem: Wt[256 kp][64]  (Whh slice, k-pair packed: Wt[kp][r*2+p], r=gate*8+jj)
//       ht[256 kp][64]  (prev h, k-pair packed: ht[kp][b*2+p])
//       red[8 warps][32 rows][RP]
// Warp w owns kp in [32w, 32w+32): computes its k-slice AND reloads it itself
// (no block sync between reload and matmul). Lane: rg=(tid>>2)&7 -> rows
// rg*4..+3, bg=tid&3 -> batches bg*8..+7 (4x8 tile, 32 f32x2 accumulators).
// Sync: one-hop monotonic counter (REDG release + acquire poll).
// ----------------------------------------------------------------------------
#define SMEM_FLOATS (2 * 256 * WP + 8 * 32 * RP)   // 41984 floats = 167936 B

__global__ void __launch_bounds__(256, 1) lstm_scan_kernel(
    const float* __restrict__ Whh_f,
    const float* __restrict__ Whh_b,
    float* __restrict__ out)
{
    extern __shared__ float sm[];
    float* Wt  = sm;                        // [256][64]
    float* ht  = sm + 256 * WP;             // [256][64]
    float* red = sm + 2 * 256 * WP;         // [8][32][RP]

    const int tid = threadIdx.x;
    const int dir = blockIdx.x >> 6;
    const int j0  = (blockIdx.x & 63) * 8;
    const float* __restrict__ Whh = dir ? Whh_b : Whh_f;

    // prologue: Wt[kp][r*2+p] from Whh rows gate*512 + j0 + jj
    {
        int r  = tid & 31;
        int gr = (r >> 3) * 512 + j0 + (r & 7);
        const float* src = Whh + (size_t)gr * 512;
        int k0 = (tid >> 5) * 64;
        for (int k = k0; k < k0 + 64; k += 4) {
            float4 v = *(const float4*)&src[k];
            int kp = k >> 1;
            Wt[kp * WP + r * 2 + 0]       = v.x;
            Wt[kp * WP + r * 2 + 1]       = v.y;
            Wt[(kp + 1) * WP + r * 2 + 0] = v.z;
            Wt[(kp + 1) * WP + r * 2 + 1] = v.w;
        }
    }
    for (int i = tid; i < 256 * WP; i += 256) ht[i] = 0.f;

    const int warp = tid >> 5;          // = k-slice owner, kp in [32w, 32w+32)
    const int lane = tid & 31;
    const int rg   = (tid >> 2) & 7;    // rows rg*4 .. rg*4+3
    const int bg   = tid & 3;           // batches bg*8 .. bg*8+7
    const int fb   = tid >> 3;          // finalize batch
    const int fj   = tid & 7;           // finalize hidden unit
    float c_state = 0.f;

    unsigned* cnt = &g_cnt[dir][0];
    const float* xg_base = &g_xg[dir][0][fb][j0 + fj];
    float* out_base = out + (size_t)fb * (TLEN * 1024) + dir * 512 + j0 + fj;
    float* hb0 = &g_hbuf[0][dir][fb][j0 + fj];
    float* hb1 = &g_hbuf[1][dir][fb][j0 + fj];

    __syncthreads();

    for (int s = 0; s < 512; s++) {
        const int t = dir ? (511 - s) : s;

        // prefetch xg (streaming; consumed ~5K cycles later)
        const float* xgp = xg_base + (size_t)t * (BAT * G4);
        float xi  = __ldcs(xgp);
        float xf  = __ldcs(xgp + 512);
        float xgv = __ldcs(xgp + 1024);
        float xo  = __ldcs(xgp + 1536);

        // ---- matmul over own k-slice: acc[i][j] += Wt[kp][row]*ht[kp][bat]
        unsigned long long acc2[4][8];
        #pragma unroll
        for (int i = 0; i < 4; i++)
            #pragma unroll
            for (int j = 0; j < 8; j++) acc2[i][j] = 0ull;

        #pragma unroll 4
        for (int kk = 0; kk < 32; kk++) {
            const float* wrow = Wt + (warp * 32 + kk) * WP;
            const float* hrow = wrow + 256 * WP;
            unsigned long long a2[4], h2[8];
            {
                ulonglong2 v0 = *(const ulonglong2*)(wrow + rg * 8);
                ulonglong2 v1 = *(const ulonglong2*)(wrow + rg * 8 + 4);
                a2[0] = v0.x; a2[1] = v0.y; a2[2] = v1.x; a2[3] = v1.y;
            }
            #pragma unroll
            for (int q = 0; q < 4; q++) {
                ulonglong2 v = *(const ulonglong2*)(hrow + bg * 16 + q * 4);
                h2[2 * q] = v.x; h2[2 * q + 1] = v.y;
            }
            #pragma unroll
            for (int i = 0; i < 4; i++)
                #pragma unroll
                for (int j = 0; j < 8; j++)
                    ffma2(acc2[i][j], a2[i], h2[j]);
        }

        // fold packed halves, write per-warp partials
        #pragma unroll
        for (int i = 0; i < 4; i++) {
            float v[8];
            #pragma unroll
            for (int j = 0; j < 8; j++)
                v[j] = lo32(acc2[i][j]) + hi32(acc2[i][j]);
            float* rp = red + warp * (32 * RP) + (rg * 4 + i) * RP + bg * 8;
            *(float4*)&rp[0] = make_float4(v[0], v[1], v[2], v[3]);
            *(float4*)&rp[4] = make_float4(v[4], v[5], v[6], v[7]);
        }
        __syncthreads();

        // ---- finalize: thread (fb, fj); rows gate*8+fj, column fb
        float hval;
        {
            float d0 = 0.f, d1 = 0.f, d2 = 0.f, d3 = 0.f;
            #pragma unroll
            for (int w = 0; w < 8; w++) {
                const float* rp = red + w * (32 * RP) + fj * RP + fb;
                d0 += rp[0];
                d1 += rp[8 * RP];
                d2 += rp[16 * RP];
                d3 += rp[24 * RP];
            }
            float ig = fsigmoid(xi + d0);
            float fg = fsigmoid(xf + d1);
            float gg = ftanh(xgv + d2);
            float og = fsigmoid(xo + d3);
            c_state = fg * c_state + ig * gg;
            hval = og * ftanh(c_state);
        }

        if (s < 511) {
            // publish h
            *((s & 1) ? hb1 : hb0) = hval;
            __threadfence();
            __syncthreads();                 // also separates red reads/writes
            if (tid == 0) red_add_release(cnt);

            // off critical path: output store
            out_base[(size_t)t * 1024] = hval;

            // wait for all 64 producers of this direction
            if (tid == 0) {
                const unsigned tgt = (unsigned)((s + 1) * NBLK_DIR);
                while ((int)(ld_acquire(cnt) - tgt) < 0) { }
            }
            __syncthreads();

            // warp-local reload of OWN k-slice (k in [64w, 64w+64)), L1-bypassed
            const float4* src = (const float4*)&g_hbuf[s & 1][dir][lane][warp * 64];
            #pragma unroll
            for (int c = 0; c < 16; c++) {
                float4 v = __ldcg(&src[c]);
                int kp = (warp * 64 + c * 4) >> 1;
                *(float2*)&ht[kp * WP + lane * 2]       = make_float2(v.x, v.y);
                *(float2*)&ht[(kp + 1) * WP + lane * 2] = make_float2(v.z, v.w);
            }
            // no __syncthreads: each warp consumes only what it wrote
        } else {
            out_base[(size_t)t * 1024] = hval;
        }
    }
}

// ----------------------------------------------------------------------------
// Launch
// ----------------------------------------------------------------------------
extern "C" void kernel_launch(void* const* d_in, const int* in_sizes, int n_in,
                              void* d_out, int out_size)
{
    (void)in_sizes; (void)n_in; (void)out_size;
    const float* x     = (const float*)d_in[0];
    const float* Wih_f = (const float*)d_in[1];
    const float* Whh_f = (const float*)d_in[2];
    const float* bih_f = (const float*)d_in[3];
    const float* bhh_f = (const float*)d_in[4];
    const float* Wih_b = (const float*)d_in[5];
    const float* Whh_b = (const float*)d_in[6];
    const float* bih_b = (const float*)d_in[7];
    const float* bhh_b = (const float*)d_in[8];
    float* out = (float*)d_out;

    static bool attr_set = false;
    if (!attr_set) {
        cudaFuncSetAttribute(lstm_scan_kernel,
                             cudaFuncAttributeMaxDynamicSharedMemorySize,
                             SMEM_FLOATS * (int)sizeof(float));
        attr_set = true;
    }

    reset_cnt_kernel<<<1, 64>>>();
    dim3 ggrid(16, 128, 2);
    gemm_xg_kernel<<<ggrid, 256>>>(x, Wih_f, Wih_b, bih_f, bhh_f, bih_b, bhh_b);
    lstm_scan_kernel<<<NBLK, 256, SMEM_FLOATS * sizeof(float)>>>(Whh_f, Whh_b, out);
}

// round 7
// speedup vs baseline: 1.2775x; 1.0629x over previous
#include <cuda_runtime.h>
#include <cstdint>

#define HID 512
#define BAT 32
#define TLEN 512
#define G4 2048
#define NBLK 128
#define NBLK_DIR 64
#define RP 36    // red row pitch: 144B rows (16B-aligned); stores/reads bank-verified

// ----------------------------------------------------------------------------
// Scratch (static __device__ — no allocations allowed)
// ----------------------------------------------------------------------------
__device__ float    g_xg[2][TLEN][BAT][G4];    // xg[dir][t][b][gate]
__device__ float    g_hbuf[2][2][BAT][HID];    // [parity][dir][b][j]
__device__ unsigned g_cnt[2][32];              // [dir][0] monotonic arrival counter

// ----------------------------------------------------------------------------
// helpers
// ----------------------------------------------------------------------------
__device__ __forceinline__ float fex2(float x)
{ float y; asm("ex2.approx.f32 %0, %1;" : "=f"(y) : "f"(x)); return y; }
__device__ __forceinline__ float frcp(float x)
{ float y; asm("rcp.approx.f32 %0, %1;" : "=f"(y) : "f"(x)); return y; }

__device__ __forceinline__ float fsigmoid(float x)
{ return frcp(1.f + fex2(-1.4426950408889634f * x)); }
__device__ __forceinline__ float ftanh(float x)
{
    float ax = fabsf(x);
    float e = fex2(-2.8853900817779268f * ax);
    float t = 1.f - 2.f * e * frcp(1.f + e);
    return copysignf(t, x);
}

__device__ __forceinline__ void red_add_release(unsigned* p)
{ asm volatile("red.release.gpu.global.add.u32 [%0], 1;" :: "l"(p) : "memory"); }
__device__ __forceinline__ unsigned ld_acquire(const unsigned* p)
{ unsigned v; asm volatile("ld.acquire.gpu.global.u32 %0, [%1];" : "=r"(v) : "l"(p) : "memory"); return v; }

// ----------------------------------------------------------------------------
// Kernel 0: zero arrival counters (stream-ordered before scan, replay-safe)
// ----------------------------------------------------------------------------
__global__ void reset_cnt_kernel()
{
    ((unsigned*)g_cnt)[threadIdx.x] = 0u;
}

// ----------------------------------------------------------------------------
// Kernel 1: xg = x @ Wih^T + bih + bhh, both dirs via blockIdx.z.
// 128x128x16 tiled SGEMM; conflict-free B reads via split-column tiles.
// ----------------------------------------------------------------------------
__global__ void __launch_bounds__(256) gemm_xg_kernel(
    const float* __restrict__ A,
    const float* __restrict__ Wf, const float* __restrict__ Wb,
    const float* __restrict__ bihf, const float* __restrict__ bhhf,
    const float* __restrict__ bihb, const float* __restrict__ bhhb)
{
    __shared__ float As[16][132];
    __shared__ float Bs[16][132];

    const int dir = blockIdx.z;
    const float* __restrict__ W   = dir ? Wb : Wf;
    const float* __restrict__ bih = dir ? bihb : bihf;
    const float* __restrict__ bhh = dir ? bhhb : bhhf;

    const int m0 = blockIdx.y * 128;
    const int n0 = blockIdx.x * 128;
    const int tid = threadIdx.x;
    const int tx = tid & 15;
    const int ty = tid >> 4;
    const int lrow = tid >> 2;
    const int lkc  = (tid & 3) * 4;

    float acc[8][8];
    #pragma unroll
    for (int i = 0; i < 8; i++)
        #pragma unroll
        for (int j = 0; j < 8; j++) acc[i][j] = 0.f;

    for (int k0 = 0; k0 < 512; k0 += 16) {
        #pragma unroll
        for (int u = 0; u < 2; u++) {
            int row = lrow + u * 64;
            float4 av = *(const float4*)&A[(size_t)(m0 + row) * 512 + k0 + lkc];
            As[lkc + 0][row] = av.x; As[lkc + 1][row] = av.y;
            As[lkc + 2][row] = av.z; As[lkc + 3][row] = av.w;
            float4 bv = *(const float4*)&W[(size_t)(n0 + row) * 512 + k0 + lkc];
            Bs[lkc + 0][row] = bv.x; Bs[lkc + 1][row] = bv.y;
            Bs[lkc + 2][row] = bv.z; Bs[lkc + 3][row] = bv.w;
        }
        __syncthreads();
        #pragma unroll
        for (int k = 0; k < 16; k++) {
            float a[8], b[8];
            *(float4*)&a[0] = *(const float4*)&As[k][ty * 8];
            *(float4*)&a[4] = *(const float4*)&As[k][ty * 8 + 4];
            *(float4*)&b[0] = *(const float4*)&Bs[k][tx * 4];
            *(float4*)&b[4] = *(const float4*)&Bs[k][64 + tx * 4];
            #pragma unroll
            for (int i = 0; i < 8; i++)
                #pragma unroll
                for (int j = 0; j < 8; j++)
                    acc[i][j] = fmaf(a[i], b[j], acc[i][j]);
        }
        __syncthreads();
    }

    float bias[8];
    #pragma unroll
    for (int j = 0; j < 4; j++) {
        int n = n0 + tx * 4 + j;
        bias[j]     = bih[n]      + bhh[n];
        bias[4 + j] = bih[n + 64] + bhh[n + 64];
    }
    #pragma unroll
    for (int i = 0; i < 8; i++) {
        int m = m0 + ty * 8 + i;
        int t = m & 511;
        int b = m >> 9;
        float* o = &g_xg[dir][t][b][n0];
        float4 v0 = make_float4(acc[i][0] + bias[0], acc[i][1] + bias[1],
                                acc[i][2] + bias[2], acc[i][3] + bias[3]);
        float4 v1 = make_float4(acc[i][4] + bias[4], acc[i][5] + bias[5],
                                acc[i][6] + bias[6], acc[i][7] + bias[7]);
        *(float4*)&o[tx * 4]      = v0;
        *(float4*)&o[64 + tx * 4] = v1;
    }
}

// ----------------------------------------------------------------------------
// Kernel 2: persistent scan. 128 blocks x 512 threads.
// dir = blk>>6; block owns 8 hidden units j0..j0+7 (32 gate rows, 32 batches).
// smem: Wt[512 k][32 r]  r = gate*8 + jj  (pitch 32, k-major)
//       ht[512 k][32 b]
//       red[16 w][32 r][RP]
// Warp w (0..15) owns k in [32w, 32w+32): computes that k-slice and reloads it
// itself from g_hbuf (no block sync needed between reload and matmul).
// Lane map: rg = (lane>>2)&7 -> rows {rg+8*gate}, bg = lane&3 -> batches bg*8..+7.
// Per thread: 4x8 fp32 tile, 1024 FFMA/step.
// Finalize: threads 0..255, (fb, fj) = (tid>>3, tid&7); sums 16 warp partials.
// Sync: per-direction monotonic counter, red.release + ld.acquire (no fences).
// ----------------------------------------------------------------------------
#define SMEM_FLOATS (2 * 512 * 32 + 16 * 32 * RP)   // 51200 floats = 204800 B

__global__ void __launch_bounds__(512, 1) lstm_scan_kernel(
    const float* __restrict__ Whh_f,
    const float* __restrict__ Whh_b,
    float* __restrict__ out)
{
    extern __shared__ float sm[];
    float* Wt  = sm;                        // [512][32]
    float* ht  = sm + 512 * 32;             // [512][32]
    float* red = sm + 2 * 512 * 32;         // [16][32][RP]

    const int tid = threadIdx.x;
    const int dir = blockIdx.x >> 6;
    const int j0  = (blockIdx.x & 63) * 8;
    const float* __restrict__ Whh = dir ? Whh_b : Whh_f;

    // prologue: Wt[k][r] from Whh row gate*512 + j0 + jj  (r = gate*8 + jj)
    {
        int r  = tid & 31;
        int gr = (r >> 3) * 512 + j0 + (r & 7);
        const float* src = Whh + (size_t)gr * 512;
        int k0 = (tid >> 5) * 32;
        for (int k = k0; k < k0 + 32; k += 4) {
            float4 v = *(const float4*)&src[k];
            Wt[(k + 0) * 32 + r] = v.x;
            Wt[(k + 1) * 32 + r] = v.y;
            Wt[(k + 2) * 32 + r] = v.z;
            Wt[(k + 3) * 32 + r] = v.w;
        }
    }
    for (int i = tid; i < 512 * 32; i += 512) ht[i] = 0.f;

    const int warp = tid >> 5;          // k-slice owner: k in [32w, 32w+32)
    const int lane = tid & 31;
    const int rg   = (lane >> 2) & 7;   // rows rg + 8*gate
    const int bg   = lane & 3;          // batches bg*8 .. bg*8+7
    const int fb   = tid >> 3;          // finalize batch (tid<256)
    const int fj   = tid & 7;           // finalize hidden unit
    float c_state = 0.f;

    unsigned* cnt = &g_cnt[dir][0];
    const float* xg_base = &g_xg[dir][0][fb & 31][j0 + fj];
    float* out_base = out + (size_t)(fb & 31) * (TLEN * 1024) + dir * 512 + j0 + fj;
    float* hb0 = &g_hbuf[0][dir][fb & 31][j0 + fj];
    float* hb1 = &g_hbuf[1][dir][fb & 31][j0 + fj];

    __syncthreads();

    for (int s = 0; s < 512; s++) {
        const int t = dir ? (511 - s) : s;

        // prefetch xg (finalize threads only; consumed after the matmul)
        float xi = 0.f, xf = 0.f, xgv = 0.f, xo = 0.f;
        if (tid < 256) {
            const float* xgp = xg_base + (size_t)t * (BAT * G4);
            xi  = __ldcs(xgp);
            xf  = __ldcs(xgp + 512);
            xgv = __ldcs(xgp + 1024);
            xo  = __ldcs(xgp + 1536);
        }

        // ---- matmul over own k-slice: acc[i][j] += Wt[k][rg+8i] * ht[k][bg*8+j]
        float acc[4][8];
        #pragma unroll
        for (int i = 0; i < 4; i++)
            #pragma unroll
            for (int j = 0; j < 8; j++) acc[i][j] = 0.f;

        #pragma unroll 8
        for (int kk = 0; kk < 32; kk++) {
            const float* wrow = Wt + (warp * 32 + kk) * 32;
            const float* hrow = wrow + 512 * 32;
            float a[4], h[8];
            a[0] = wrow[rg];
            a[1] = wrow[rg + 8];
            a[2] = wrow[rg + 16];
            a[3] = wrow[rg + 24];
            *(float4*)&h[0] = *(const float4*)&hrow[bg * 8];
            *(float4*)&h[4] = *(const float4*)&hrow[bg * 8 + 4];
            #pragma unroll
            for (int i = 0; i < 4; i++)
                #pragma unroll
                for (int j = 0; j < 8; j++)
                    acc[i][j] = fmaf(a[i], h[j], acc[i][j]);
        }

        // ---- write per-warp partials: row = rg + 8i, cols bg*8..+7
        //      STS.128 start bank = (4rg + 8bg) mod 32 -> conflict-free phases
        #pragma unroll
        for (int i = 0; i < 4; i++) {
            float* rp = red + warp * (32 * RP) + (rg + 8 * i) * RP + bg * 8;
            *(float4*)&rp[0] = make_float4(acc[i][0], acc[i][1], acc[i][2], acc[i][3]);
            *(float4*)&rp[4] = make_float4(acc[i][4], acc[i][5], acc[i][6], acc[i][7]);
        }
        __syncthreads();

        // ---- finalize on threads 0..255: cell (fb, j0+fj); rows gate*8+fj
        //      scalar reads bank = (4fj + fb) mod 32 -> conflict-free
        float hval = 0.f;
        if (tid < 256) {
            float d0 = 0.f, d1 = 0.f, d2 = 0.f, d3 = 0.f;
            #pragma unroll
            for (int w = 0; w < 16; w++) {
                const float* rp = red + w * (32 * RP) + fj * RP + fb;
                d0 += rp[0];
                d1 += rp[8 * RP];
                d2 += rp[16 * RP];
                d3 += rp[24 * RP];
            }
            float ig = fsigmoid(xi + d0);
            float fg = fsigmoid(xf + d1);
            float gg = ftanh(xgv + d2);
            float og = fsigmoid(xo + d3);
            c_state = fg * c_state + ig * gg;
            hval = og * ftanh(c_state);
            if (s < 511)
                *((s & 1) ? hb1 : hb0) = hval;   // publish h (plain store)
        }

        if (s < 511) {
            __syncthreads();                     // all publishes done (cta scope)
            if (tid == 0) red_add_release(cnt);  // release covers block's stores

            // off critical path: output store
            if (tid < 256)
                out_base[(size_t)t * 1024] = hval;

            // wait for all 64 producers of this direction
            if (tid == 0) {
                const unsigned tgt = (unsigned)((s + 1) * NBLK_DIR);
                while ((int)(ld_acquire(cnt) - tgt) < 0) { }
            }
            __syncthreads();

            // warp-local reload of OWN k-slice: k in [32w, 32w+32), lane = batch
            const float4* src = (const float4*)&g_hbuf[s & 1][dir][lane][warp * 32];
            #pragma unroll
            for (int c = 0; c < 8; c++) {
                float4 v = __ldcg(&src[c]);
                int k = warp * 32 + c * 4;
                ht[(k + 0) * 32 + lane] = v.x;
                ht[(k + 1) * 32 + lane] = v.y;
                ht[(k + 2) * 32 + lane] = v.z;
                ht[(k + 3) * 32 + lane] = v.w;
            }
            // no block sync needed: each warp consumes only its own k-slice
        } else {
            if (tid < 256)
                out_base[(size_t)t * 1024] = hval;
        }
    }
}

// ----------------------------------------------------------------------------
// Launch
// ----------------------------------------------------------------------------
extern "C" void kernel_launch(void* const* d_in, const int* in_sizes, int n_in,
                              void* d_out, int out_size)
{
    (void)in_sizes; (void)n_in; (void)out_size;
    const float* x     = (const float*)d_in[0];
    const float* Wih_f = (const float*)d_in[1];
    const float* Whh_f = (const float*)d_in[2];
    const float* bih_f = (const float*)d_in[3];
    const float* bhh_f = (const float*)d_in[4];
    const float* Wih_b = (const float*)d_in[5];
    const float* Whh_b = (const float*)d_in[6];
    const float* bih_b = (const float*)d_in[7];
    const float* bhh_b = (const float*)d_in[8];
    float* out = (float*)d_out;

    static bool attr_set = false;
    if (!attr_set) {
        cudaFuncSetAttribute(lstm_scan_kernel,
                             cudaFuncAttributeMaxDynamicSharedMemorySize,
                             SMEM_FLOATS * (int)sizeof(float));
        attr_set = true;
    }

    reset_cnt_kernel<<<1, 64>>>();
    dim3 ggrid(16, 128, 2);
    gemm_xg_kernel<<<ggrid, 256>>>(x, Wih_f, Wih_b, bih_f, bhh_f, bih_b, bhh_b);
    lstm_scan_kernel<<<NBLK, 512, SMEM_FLOATS * sizeof(float)>>>(Whh_f, Whh_b, out);
}

// round 8
// speedup vs baseline: 2.7219x; 2.1307x over previous
#include <cuda_runtime.h>
#include <cuda_fp16.h>
#include <cstdint>

#define HID 512
#define BAT 32
#define TLEN 512
#define G4 2048
#define NBLK 128
#define NBLK_DIR 64
#define HP 40    // ht2s row pitch (uint32): bank = 8*kp + lane -> conflict-free
#define RP2 36   // red row pitch (floats): finalize bank = 4*fj + fb -> bijective

// ----------------------------------------------------------------------------
// Scratch (static __device__ — no allocations allowed)
// ----------------------------------------------------------------------------
__device__ float    g_xg[2][TLEN][BAT][G4];    // xg[dir][t][b][gate]
__device__ uint32_t g_h2[2][2][256][32];       // [parity][dir][kp][b] packed half2 (k even/odd)
__device__ unsigned g_cnt[2][32];              // [dir][0] monotonic arrival counter

// ----------------------------------------------------------------------------
// helpers
// ----------------------------------------------------------------------------
__device__ __forceinline__ float fex2(float x)
{ float y; asm("ex2.approx.f32 %0, %1;" : "=f"(y) : "f"(x)); return y; }
__device__ __forceinline__ float frcp(float x)
{ float y; asm("rcp.approx.f32 %0, %1;" : "=f"(y) : "f"(x)); return y; }

__device__ __forceinline__ float fsigmoid(float x)
{ return frcp(1.f + fex2(-1.4426950408889634f * x)); }
__device__ __forceinline__ float ftanh(float x)
{
    float ax = fabsf(x);
    float e = fex2(-2.8853900817779268f * ax);
    float t = 1.f - 2.f * e * frcp(1.f + e);
    return copysignf(t, x);
}

__device__ __forceinline__ void red_add_release(unsigned* p)
{ asm volatile("red.release.gpu.global.add.u32 [%0], 1;" :: "l"(p) : "memory"); }
__device__ __forceinline__ unsigned ld_acquire(const unsigned* p)
{ unsigned v; asm volatile("ld.acquire.gpu.global.u32 %0, [%1];" : "=r"(v) : "l"(p) : "memory"); return v; }

__device__ __forceinline__ uint32_t pack_h2(float a, float b)
{
    __half2 h = __floats2half2_rn(a, b);   // low = a (even k), high = b (odd k)
    return *(uint32_t*)&h;
}

__device__ __forceinline__ void mma16816(float& d0, float& d1, float& d2, float& d3,
                                         uint32_t a0, uint32_t a1, uint32_t a2, uint32_t a3,
                                         uint32_t b0, uint32_t b1)
{
    asm("mma.sync.aligned.m16n8k16.row.col.f32.f16.f16.f32 "
        "{%0,%1,%2,%3}, {%4,%5,%6,%7}, {%8,%9}, {%0,%1,%2,%3};"
        : "+f"(d0), "+f"(d1), "+f"(d2), "+f"(d3)
        : "r"(a0), "r"(a1), "r"(a2), "r"(a3), "r"(b0), "r"(b1));
}

// ----------------------------------------------------------------------------
// Kernel 0: zero arrival counters (stream-ordered before scan, replay-safe)
// ----------------------------------------------------------------------------
__global__ void reset_cnt_kernel()
{
    ((unsigned*)g_cnt)[threadIdx.x] = 0u;
}

// ----------------------------------------------------------------------------
// Kernel 1: xg = x @ Wih^T + bih + bhh, both dirs via blockIdx.z.
// 128x128x16 tiled SGEMM; conflict-free B reads via split-column tiles.
// ----------------------------------------------------------------------------
__global__ void __launch_bounds__(256) gemm_xg_kernel(
    const float* __restrict__ A,
    const float* __restrict__ Wf, const float* __restrict__ Wb,
    const float* __restrict__ bihf, const float* __restrict__ bhhf,
    const float* __restrict__ bihb, const float* __restrict__ bhhb)
{
    __shared__ float As[16][132];
    __shared__ float Bs[16][132];

    const int dir = blockIdx.z;
    const float* __restrict__ W   = dir ? Wb : Wf;
    const float* __restrict__ bih = dir ? bihb : bihf;
    const float* __restrict__ bhh = dir ? bhhb : bhhf;

    const int m0 = blockIdx.y * 128;
    const int n0 = blockIdx.x * 128;
    const int tid = threadIdx.x;
    const int tx = tid & 15;
    const int ty = tid >> 4;
    const int lrow = tid >> 2;
    const int lkc  = (tid & 3) * 4;

    float acc[8][8];
    #pragma unroll
    for (int i = 0; i < 8; i++)
        #pragma unroll
        for (int j = 0; j < 8; j++) acc[i][j] = 0.f;

    for (int k0 = 0; k0 < 512; k0 += 16) {
        #pragma unroll
        for (int u = 0; u < 2; u++) {
            int row = lrow + u * 64;
            float4 av = *(const float4*)&A[(size_t)(m0 + row) * 512 + k0 + lkc];
            As[lkc + 0][row] = av.x; As[lkc + 1][row] = av.y;
            As[lkc + 2][row] = av.z; As[lkc + 3][row] = av.w;
            float4 bv = *(const float4*)&W[(size_t)(n0 + row) * 512 + k0 + lkc];
            Bs[lkc + 0][row] = bv.x; Bs[lkc + 1][row] = bv.y;
            Bs[lkc + 2][row] = bv.z; Bs[lkc + 3][row] = bv.w;
        }
        __syncthreads();
        #pragma unroll
        for (int k = 0; k < 16; k++) {
            float a[8], b[8];
            *(float4*)&a[0] = *(const float4*)&As[k][ty * 8];
            *(float4*)&a[4] = *(const float4*)&As[k][ty * 8 + 4];
            *(float4*)&b[0] = *(const float4*)&Bs[k][tx * 4];
            *(float4*)&b[4] = *(const float4*)&Bs[k][64 + tx * 4];
            #pragma unroll
            for (int i = 0; i < 8; i++)
                #pragma unroll
                for (int j = 0; j < 8; j++)
                    acc[i][j] = fmaf(a[i], b[j], acc[i][j]);
        }
        __syncthreads();
    }

    float bias[8];
    #pragma unroll
    for (int j = 0; j < 4; j++) {
        int n = n0 + tx * 4 + j;
        bias[j]     = bih[n]      + bhh[n];
        bias[4 + j] = bih[n + 64] + bhh[n + 64];
    }
    #pragma unroll
    for (int i = 0; i < 8; i++) {
        int m = m0 + ty * 8 + i;
        int t = m & 511;
        int b = m >> 9;
        float* o = &g_xg[dir][t][b][n0];
        float4 v0 = make_float4(acc[i][0] + bias[0], acc[i][1] + bias[1],
                                acc[i][2] + bias[2], acc[i][3] + bias[3]);
        float4 v1 = make_float4(acc[i][4] + bias[4], acc[i][5] + bias[5],
                                acc[i][6] + bias[6], acc[i][7] + bias[7]);
        *(float4*)&o[tx * 4]      = v0;
        *(float4*)&o[64 + tx * 4] = v1;
    }
}

// ----------------------------------------------------------------------------
// Kernel 2: persistent scan — TENSOR PIPE recurrent matmul.
// 128 blocks x 512 threads. dir = blk>>6; block owns 8 hidden units ->
// 32 gate rows x 32 batches x K=512 per step.
// mma.m16n8k16 f16->f32: warp = (m: row-tile of 16) + 2*(kh: k-half) + 4*(n: col-tile of 8).
// A (Whh slice, fp16) lives in REGISTERS: 16 ktiles x 4 regs, loaded once.
// B (h, fp16) in smem ht2s[kp][b] (uint32 half2 of k-pair), pitch HP=40:
//   LDS bank = 8c + g -> all 32 banks distinct. Reload from g_h2 is 128B-coalesced.
// red[2 kh][32 r][RP2]: only 2 partials per output; finalize banks bijective.
// Sync: per-direction monotonic counter (red.release + ld.acquire), as R7.
// ----------------------------------------------------------------------------
#define SMEM_WORDS (256 * HP + 2 * 32 * RP2)   // 12544 words = 50176 B

__global__ void __launch_bounds__(512, 1) lstm_scan_kernel(
    const float* __restrict__ Whh_f,
    const float* __restrict__ Whh_b,
    float* __restrict__ out)
{
    extern __shared__ uint32_t smu[];
    uint32_t* ht2s = smu;                         // [256][HP]
    float*    red  = (float*)(smu + 256 * HP);    // [2][32][RP2]

    const int tid = threadIdx.x;
    const int dir = blockIdx.x >> 6;
    const int j0  = (blockIdx.x & 63) * 8;
    const float* __restrict__ Whh = dir ? Whh_b : Whh_f;

    const int warp = tid >> 5;
    const int lane = tid & 31;
    const int wm = warp & 1;            // row tile (rows wm*16 .. +15)
    const int kh = (warp >> 1) & 1;     // k half   (k in [kh*256, kh*256+256))
    const int wn = warp >> 2;           // col tile (batches wn*8 .. +7)
    const int g  = lane >> 2;           // 0..7
    const int c  = lane & 3;            // 0..3

    // ---- A fragments (fp16) into registers, once. rows r = gate*8 + jj.
    uint32_t afrag[16][4];
    {
        int r0 = wm * 16 + g;           // rows r0 and r0+8
        const float* rowA = Whh + (size_t)((r0 >> 3) * 512 + j0 + (r0 & 7)) * 512;
        const float* rowB = Whh + (size_t)((((r0 + 8) >> 3)) * 512 + j0 + ((r0 + 8) & 7)) * 512;
        #pragma unroll
        for (int kt = 0; kt < 16; kt++) {
            int kb = kh * 256 + kt * 16 + 2 * c;
            afrag[kt][0] = pack_h2(rowA[kb],     rowA[kb + 1]);
            afrag[kt][1] = pack_h2(rowB[kb],     rowB[kb + 1]);
            afrag[kt][2] = pack_h2(rowA[kb + 8], rowA[kb + 9]);
            afrag[kt][3] = pack_h2(rowB[kb + 8], rowB[kb + 9]);
        }
    }

    // h_{-1} = 0
    for (int i = tid; i < 256 * HP; i += 512) ht2s[i] = 0u;

    const int fb = tid >> 3;            // finalize batch (tid < 256)
    const int fj = tid & 7;             // finalize hidden unit
    float c_state = 0.f;

    unsigned* cnt = &g_cnt[dir][0];
    const float* xg_base = &g_xg[dir][0][fb & 31][j0 + fj];
    float* out_base = out + (size_t)(fb & 31) * (TLEN * 1024) + dir * 512 + j0 + fj;
    uint32_t* h2_base0 = &g_h2[0][dir][(j0 + fj) >> 1][fb & 31];
    uint32_t* h2_base1 = &g_h2[1][dir][(j0 + fj) >> 1][fb & 31];

    __syncthreads();

    for (int s = 0; s < 512; s++) {
        const int t = dir ? (511 - s) : s;

        // prefetch xg (finalize threads only)
        float xi = 0.f, xf = 0.f, xgv = 0.f, xo = 0.f;
        if (tid < 256) {
            const float* xgp = xg_base + (size_t)t * (BAT * G4);
            xi  = __ldcs(xgp);
            xf  = __ldcs(xgp + 512);
            xgv = __ldcs(xgp + 1024);
            xo  = __ldcs(xgp + 1536);
        }

        // ---- tensor-pipe matmul: D[32r][32b] partial over this warp's k half
        float d0 = 0.f, d1 = 0.f, d2 = 0.f, d3 = 0.f;
        #pragma unroll
        for (int kt = 0; kt < 16; kt++) {
            int kp0 = kh * 128 + kt * 8;
            uint32_t b0 = ht2s[(kp0 + c) * HP + wn * 8 + g];
            uint32_t b1 = ht2s[(kp0 + 4 + c) * HP + wn * 8 + g];
            mma16816(d0, d1, d2, d3,
                     afrag[kt][0], afrag[kt][1], afrag[kt][2], afrag[kt][3],
                     b0, b1);
        }

        // ---- store D fragment: rows wm*16+g (+8), cols wn*8 + 2c (+1)
        {
            float* rp = red + kh * (32 * RP2) + (wm * 16 + g) * RP2 + wn * 8 + 2 * c;
            *(float2*)rp            = make_float2(d0, d1);
            *(float2*)(rp + 8 * RP2) = make_float2(d2, d3);
        }
        __syncthreads();

        // ---- finalize on threads 0..255: cell (fb, j0+fj); rows gate*8+fj
        float hval = 0.f;
        if (tid < 256) {
            float dd[4];
            #pragma unroll
            for (int gate = 0; gate < 4; gate++) {
                int off = (gate * 8 + fj) * RP2 + fb;
                dd[gate] = red[off] + red[32 * RP2 + off];
            }
            float ig = fsigmoid(xi  + dd[0]);
            float fg = fsigmoid(xf  + dd[1]);
            float gg = ftanh(xgv + dd[2]);
            float og = fsigmoid(xo  + dd[3]);
            c_state = fg * c_state + ig * gg;
            hval = og * ftanh(c_state);

            if (s < 511) {
                // publish packed half2 (even fj pairs with odd fj via shfl)
                float hpart = __shfl_xor_sync(0xffffffffu, hval, 1);
                if ((fj & 1) == 0) {
                    uint32_t v = pack_h2(hval, hpart);
                    *((s & 1) ? h2_base1 : h2_base0) = v;
                }
            }
        }

        if (s < 511) {
            __syncthreads();                     // all publishes done (cta scope)
            if (tid == 0) red_add_release(cnt);  // release covers block's stores

            // off critical path: fp32 output store
            if (tid < 256)
                out_base[(size_t)t * 1024] = hval;

            // wait for all 64 producers of this direction
            if (tid == 0) {
                const unsigned tgt = (unsigned)((s + 1) * NBLK_DIR);
                while ((int)(ld_acquire(cnt) - tgt) < 0) { }
            }
            __syncthreads();

            // reload: warp w owns kp in [16w, 16w+16); 128B-coalesced rows
            const uint32_t* src = &g_h2[s & 1][dir][0][0];
            #pragma unroll
            for (int i = 0; i < 16; i++) {
                int kp = warp * 16 + i;
                uint32_t v = __ldcg(&src[kp * 32 + lane]);
                ht2s[kp * HP + lane] = v;
            }
            __syncthreads();                     // mma consumes cross-warp slices
        } else {
            if (tid < 256)
                out_base[(size_t)t * 1024] = hval;
        }
    }
}

// ----------------------------------------------------------------------------
// Launch
// ----------------------------------------------------------------------------
extern "C" void kernel_launch(void* const* d_in, const int* in_sizes, int n_in,
                              void* d_out, int out_size)
{
    (void)in_sizes; (void)n_in; (void)out_size;
    const float* x     = (const float*)d_in[0];
    const float* Wih_f = (const float*)d_in[1];
    const float* Whh_f = (const float*)d_in[2];
    const float* bih_f = (const float*)d_in[3];
    const float* bhh_f = (const float*)d_in[4];
    const float* Wih_b = (const float*)d_in[5];
    const float* Whh_b = (const float*)d_in[6];
    const float* bih_b = (const float*)d_in[7];
    const float* bhh_b = (const float*)d_in[8];
    float* out = (float*)d_out;

    static bool attr_set = false;
    if (!attr_set) {
        cudaFuncSetAttribute(lstm_scan_kernel,
                             cudaFuncAttributeMaxDynamicSharedMemorySize,
                             SMEM_WORDS * (int)sizeof(uint32_t));
        attr_set = true;
    }

    reset_cnt_kernel<<<1, 64>>>();
    dim3 ggrid(16, 128, 2);
    gemm_xg_kernel<<<ggrid, 256>>>(x, Wih_f, Wih_b, bih_f, bhh_f, bih_b, bhh_b);
    lstm_scan_kernel<<<NBLK, 512, SMEM_WORDS * sizeof(uint32_t)>>>(Whh_f, Whh_b, out);
}

// round 9
// speedup vs baseline: 3.9400x; 1.4475x over previous
#include <cuda_runtime.h>
#include <cuda_fp16.h>
#include <cstdint>

#define HID 512
#define BAT 32
#define TLEN 512
#define G4 2048
#define NBLK 128
#define NBLK_DIR 64
#define HP 40    // scan ht2s row pitch (uint32): conflict-free
#define RP2 36   // scan red row pitch (floats): finalize banks bijective
#define GP 20    // gemm smem row pitch (uint32): frag reads + STS conflict-free

#define X_WORDS (16384 * 256)
#define W_WORDS (2048 * 256)

// ----------------------------------------------------------------------------
// Scratch (static __device__ — no allocations allowed)
// ----------------------------------------------------------------------------
__device__ float    g_xg[2][TLEN][BAT][G4];    // xg[dir][t][b][gate]
__device__ uint32_t g_h2[2][2][256][32];       // [parity][dir][kp][b] packed half2
__device__ unsigned g_cnt[2][32];              // [dir][0] monotonic arrival counter
__device__ uint32_t g_xh2[X_WORDS];            // x as half2 k-pairs [m][kp], m=b*512+t
__device__ uint32_t g_wh2[2][W_WORDS];         // Wih as half2 k-pairs [n][kp]

// ----------------------------------------------------------------------------
// helpers
// ----------------------------------------------------------------------------
__device__ __forceinline__ float fex2(float x)
{ float y; asm("ex2.approx.f32 %0, %1;" : "=f"(y) : "f"(x)); return y; }
__device__ __forceinline__ float frcp(float x)
{ float y; asm("rcp.approx.f32 %0, %1;" : "=f"(y) : "f"(x)); return y; }

__device__ __forceinline__ float fsigmoid(float x)
{ return frcp(1.f + fex2(-1.4426950408889634f * x)); }
__device__ __forceinline__ float ftanh(float x)
{
    float ax = fabsf(x);
    float e = fex2(-2.8853900817779268f * ax);
    float t = 1.f - 2.f * e * frcp(1.f + e);
    return copysignf(t, x);
}

__device__ __forceinline__ void red_add_release(unsigned* p)
{ asm volatile("red.release.gpu.global.add.u32 [%0], 1;" :: "l"(p) : "memory"); }
__device__ __forceinline__ unsigned ld_acquire(const unsigned* p)
{ unsigned v; asm volatile("ld.acquire.gpu.global.u32 %0, [%1];" : "=r"(v) : "l"(p) : "memory"); return v; }

__device__ __forceinline__ uint32_t pack_h2(float a, float b)
{
    __half2 h = __floats2half2_rn(a, b);
    return *(uint32_t*)&h;
}

__device__ __forceinline__ void mma16816(float& d0, float& d1, float& d2, float& d3,
                                         uint32_t a0, uint32_t a1, uint32_t a2, uint32_t a3,
                                         uint32_t b0, uint32_t b1)
{
    asm("mma.sync.aligned.m16n8k16.row.col.f32.f16.f16.f32 "
        "{%0,%1,%2,%3}, {%4,%5,%6,%7}, {%8,%9}, {%0,%1,%2,%3};"
        : "+f"(d0), "+f"(d1), "+f"(d2), "+f"(d3)
        : "r"(a0), "r"(a1), "r"(a2), "r"(a3), "r"(b0), "r"(b1));
}

// ----------------------------------------------------------------------------
// Kernel 0a: zero arrival counters
// ----------------------------------------------------------------------------
__global__ void reset_cnt_kernel()
{
    ((unsigned*)g_cnt)[threadIdx.x] = 0u;
}

// ----------------------------------------------------------------------------
// Kernel 0b: convert x / Wih_f / Wih_b to half2 k-pair layout.
// 8 output words (16 floats) per thread; 2560 blocks x 256 covers all exactly.
// ----------------------------------------------------------------------------
__global__ void __launch_bounds__(256) cvt_kernel(
    const float* __restrict__ x,
    const float* __restrict__ Wf,
    const float* __restrict__ Wb)
{
    size_t w = ((size_t)blockIdx.x * 256 + threadIdx.x) * 8;
    const float* src;
    uint32_t* dst;
    if (w < X_WORDS)                     { src = x  + 2 * w;               dst = g_xh2 + w; }
    else if (w < X_WORDS + W_WORDS)      { src = Wf + 2 * (w - X_WORDS);   dst = g_wh2[0] + (w - X_WORDS); }
    else                                 { src = Wb + 2 * (w - X_WORDS - W_WORDS);
                                           dst = g_wh2[1] + (w - X_WORDS - W_WORDS); }
    const float4* s = (const float4*)src;
    #pragma unroll
    for (int i = 0; i < 4; i++) {
        float4 v = s[i];
        dst[2 * i]     = pack_h2(v.x, v.y);
        dst[2 * i + 1] = pack_h2(v.z, v.w);
    }
}

// ----------------------------------------------------------------------------
// Kernel 1: tensor-core input GEMM. xg = x @ Wih^T + bih + bhh.
// Grid (16 n-tiles, 128 m-tiles, 2 dirs); 256 threads = 8 warps (4m x 2n),
// warp tile 32x64, mma.m16n8k16 fp16->fp32. K chunks of 32 (16 kp words),
// register prefetch + double-buffered smem, pitch GP=20:
//   frag reads bank (g*20+c) -> 32 distinct; uint4 STS phases {20r+8h} distinct.
// ----------------------------------------------------------------------------
__global__ void __launch_bounds__(256) gemm_xg_tc_kernel(
    const float* __restrict__ bihf, const float* __restrict__ bhhf,
    const float* __restrict__ bihb, const float* __restrict__ bhhb)
{
    __shared__ uint32_t smg[2][2][128 * GP];

    const int dir = blockIdx.z;
    const int n0 = blockIdx.x * 128;
    const int m0 = blockIdx.y * 128;
    const uint32_t* __restrict__ A = g_xh2 + (size_t)m0 * 256;
    const uint32_t* __restrict__ B = g_wh2[dir] + (size_t)n0 * 256;
    const float* __restrict__ bih = dir ? bihb : bihf;
    const float* __restrict__ bhh = dir ? bhhb : bhhf;

    const int tid = threadIdx.x;
    const int warp = tid >> 5, lane = tid & 31;
    const int g = lane >> 2, c = lane & 3;
    const int wm = warp & 3;            // rows wm*32 .. +31
    const int wn = warp >> 2;           // cols wn*64 .. +63
    const int lrow  = tid & 127;        // load row
    const int lhalf = tid >> 7;         // load k-half (8 words)

    float acc[2][8][4];
    #pragma unroll
    for (int mt = 0; mt < 2; mt++)
        #pragma unroll
        for (int nt = 0; nt < 8; nt++)
            #pragma unroll
            for (int q = 0; q < 4; q++) acc[mt][nt][q] = 0.f;

    uint4 pa0, pa1, pb0, pb1;
    {
        const uint4* pa = (const uint4*)(A + (size_t)lrow * 256 + lhalf * 8);
        pa0 = pa[0]; pa1 = pa[1];
        const uint4* pb = (const uint4*)(B + (size_t)lrow * 256 + lhalf * 8);
        pb0 = pb[0]; pb1 = pb[1];
    }
    {
        uint4* as = (uint4*)&smg[0][0][lrow * GP + lhalf * 8];
        as[0] = pa0; as[1] = pa1;
        uint4* bs = (uint4*)&smg[0][1][lrow * GP + lhalf * 8];
        bs[0] = pb0; bs[1] = pb1;
    }
    __syncthreads();

    for (int kc = 0; kc < 16; kc++) {
        if (kc < 15) {
            const uint4* pa = (const uint4*)(A + (size_t)lrow * 256 + (kc + 1) * 16 + lhalf * 8);
            pa0 = pa[0]; pa1 = pa[1];
            const uint4* pb = (const uint4*)(B + (size_t)lrow * 256 + (kc + 1) * 16 + lhalf * 8);
            pb0 = pb[0]; pb1 = pb[1];
        }
        const uint32_t* as = smg[kc & 1][0];
        const uint32_t* bs = smg[kc & 1][1];
        #pragma unroll
        for (int ks = 0; ks < 2; ks++) {
            uint32_t af[2][4];
            #pragma unroll
            for (int mt = 0; mt < 2; mt++) {
                int r = wm * 32 + mt * 16 + g;
                af[mt][0] = as[r * GP + ks * 8 + c];
                af[mt][1] = as[(r + 8) * GP + ks * 8 + c];
                af[mt][2] = as[r * GP + ks * 8 + 4 + c];
                af[mt][3] = as[(r + 8) * GP + ks * 8 + 4 + c];
            }
            #pragma unroll
            for (int nt = 0; nt < 8; nt++) {
                int nr = wn * 64 + nt * 8 + g;
                uint32_t b0 = bs[nr * GP + ks * 8 + c];
                uint32_t b1 = bs[nr * GP + ks * 8 + 4 + c];
                #pragma unroll
                for (int mt = 0; mt < 2; mt++)
                    mma16816(acc[mt][nt][0], acc[mt][nt][1], acc[mt][nt][2], acc[mt][nt][3],
                             af[mt][0], af[mt][1], af[mt][2], af[mt][3], b0, b1);
            }
        }
        if (kc < 15) {
            uint4* asw = (uint4*)&smg[(kc + 1) & 1][0][lrow * GP + lhalf * 8];
            asw[0] = pa0; asw[1] = pa1;
            uint4* bsw = (uint4*)&smg[(kc + 1) & 1][1][lrow * GP + lhalf * 8];
            bsw[0] = pb0; bsw[1] = pb1;
            __syncthreads();
        }
    }

    // epilogue: bias + fp32 store to g_xg
    float bias0[8], bias1[8];
    #pragma unroll
    for (int nt = 0; nt < 8; nt++) {
        int n = n0 + wn * 64 + nt * 8 + 2 * c;
        bias0[nt] = bih[n] + bhh[n];
        bias1[nt] = bih[n + 1] + bhh[n + 1];
    }
    #pragma unroll
    for (int mt = 0; mt < 2; mt++) {
        #pragma unroll
        for (int rr = 0; rr < 2; rr++) {
            int m = m0 + wm * 32 + mt * 16 + g + rr * 8;
            int t = m & 511;
            int b = m >> 9;
            float* o = &g_xg[dir][t][b][n0 + wn * 64];
            #pragma unroll
            for (int nt = 0; nt < 8; nt++) {
                float2 v = make_float2(acc[mt][nt][rr * 2 + 0] + bias0[nt],
                                       acc[mt][nt][rr * 2 + 1] + bias1[nt]);
                *(float2*)&o[nt * 8 + 2 * c] = v;
            }
        }
    }
}

// ----------------------------------------------------------------------------
// Kernel 2: persistent scan — tensor-pipe recurrent matmul (as R8).
// ----------------------------------------------------------------------------
#define SMEM_WORDS (256 * HP + 2 * 32 * RP2)   // 12544 words = 50176 B

__global__ void __launch_bounds__(512, 1) lstm_scan_kernel(
    const float* __restrict__ Whh_f,
    const float* __restrict__ Whh_b,
    float* __restrict__ out)
{
    extern __shared__ uint32_t smu[];
    uint32_t* ht2s = smu;                         // [256][HP]
    float*    red  = (float*)(smu + 256 * HP);    // [2][32][RP2]

    const int tid = threadIdx.x;
    const int dir = blockIdx.x >> 6;
    const int j0  = (blockIdx.x & 63) * 8;
    const float* __restrict__ Whh = dir ? Whh_b : Whh_f;

    const int warp = tid >> 5;
    const int lane = tid & 31;
    const int wm = warp & 1;
    const int kh = (warp >> 1) & 1;
    const int wn = warp >> 2;
    const int g  = lane >> 2;
    const int c  = lane & 3;

    uint32_t afrag[16][4];
    {
        int r0 = wm * 16 + g;
        const float* rowA = Whh + (size_t)((r0 >> 3) * 512 + j0 + (r0 & 7)) * 512;
        const float* rowB = Whh + (size_t)((((r0 + 8) >> 3)) * 512 + j0 + ((r0 + 8) & 7)) * 512;
        #pragma unroll
        for (int kt = 0; kt < 16; kt++) {
            int kb = kh * 256 + kt * 16 + 2 * c;
            afrag[kt][0] = pack_h2(rowA[kb],     rowA[kb + 1]);
            afrag[kt][1] = pack_h2(rowB[kb],     rowB[kb + 1]);
            afrag[kt][2] = pack_h2(rowA[kb + 8], rowA[kb + 9]);
            afrag[kt][3] = pack_h2(rowB[kb + 8], rowB[kb + 9]);
        }
    }

    for (int i = tid; i < 256 * HP; i += 512) ht2s[i] = 0u;

    const int fb = tid >> 3;
    const int fj = tid & 7;
    float c_state = 0.f;

    unsigned* cnt = &g_cnt[dir][0];
    const float* xg_base = &g_xg[dir][0][fb & 31][j0 + fj];
    float* out_base = out + (size_t)(fb & 31) * (TLEN * 1024) + dir * 512 + j0 + fj;
    uint32_t* h2_base0 = &g_h2[0][dir][(j0 + fj) >> 1][fb & 31];
    uint32_t* h2_base1 = &g_h2[1][dir][(j0 + fj) >> 1][fb & 31];

    __syncthreads();

    for (int s = 0; s < 512; s++) {
        const int t = dir ? (511 - s) : s;

        float xi = 0.f, xf = 0.f, xgv = 0.f, xo = 0.f;
        if (tid < 256) {
            const float* xgp = xg_base + (size_t)t * (BAT * G4);
            xi  = __ldcs(xgp);
            xf  = __ldcs(xgp + 512);
            xgv = __ldcs(xgp + 1024);
            xo  = __ldcs(xgp + 1536);
        }

        float d0 = 0.f, d1 = 0.f, d2 = 0.f, d3 = 0.f;
        #pragma unroll
        for (int kt = 0; kt < 16; kt++) {
            int kp0 = kh * 128 + kt * 8;
            uint32_t b0 = ht2s[(kp0 + c) * HP + wn * 8 + g];
            uint32_t b1 = ht2s[(kp0 + 4 + c) * HP + wn * 8 + g];
            mma16816(d0, d1, d2, d3,
                     afrag[kt][0], afrag[kt][1], afrag[kt][2], afrag[kt][3],
                     b0, b1);
        }

        {
            float* rp = red + kh * (32 * RP2) + (wm * 16 + g) * RP2 + wn * 8 + 2 * c;
            *(float2*)rp             = make_float2(d0, d1);
            *(float2*)(rp + 8 * RP2) = make_float2(d2, d3);
        }
        __syncthreads();

        float hval = 0.f;
        if (tid < 256) {
            float dd[4];
            #pragma unroll
            for (int gate = 0; gate < 4; gate++) {
                int off = (gate * 8 + fj) * RP2 + fb;
                dd[gate] = red[off] + red[32 * RP2 + off];
            }
            float ig = fsigmoid(xi  + dd[0]);
            float fg = fsigmoid(xf  + dd[1]);
            float gg = ftanh(xgv + dd[2]);
            float og = fsigmoid(xo  + dd[3]);
            c_state = fg * c_state + ig * gg;
            hval = og * ftanh(c_state);

            if (s < 511) {
                float hpart = __shfl_xor_sync(0xffffffffu, hval, 1);
                if ((fj & 1) == 0) {
                    uint32_t v = pack_h2(hval, hpart);
                    *((s & 1) ? h2_base1 : h2_base0) = v;
                }
            }
        }

        if (s < 511) {
            __syncthreads();
            if (tid == 0) red_add_release(cnt);

            if (tid < 256)
                out_base[(size_t)t * 1024] = hval;

            if (tid == 0) {
                const unsigned tgt = (unsigned)((s + 1) * NBLK_DIR);
                while ((int)(ld_acquire(cnt) - tgt) < 0) { }
            }
            __syncthreads();

            const uint32_t* src = &g_h2[s & 1][dir][0][0];
            #pragma unroll
            for (int i = 0; i < 16; i++) {
                int kp = warp * 16 + i;
                uint32_t v = __ldcg(&src[kp * 32 + lane]);
                ht2s[kp * HP + lane] = v;
            }
            __syncthreads();
        } else {
            if (tid < 256)
                out_base[(size_t)t * 1024] = hval;
        }
    }
}

// ----------------------------------------------------------------------------
// Launch
// ----------------------------------------------------------------------------
extern "C" void kernel_launch(void* const* d_in, const int* in_sizes, int n_in,
                              void* d_out, int out_size)
{
    (void)in_sizes; (void)n_in; (void)out_size;
    const float* x     = (const float*)d_in[0];
    const float* Wih_f = (const float*)d_in[1];
    const float* Whh_f = (const float*)d_in[2];
    const float* bih_f = (const float*)d_in[3];
    const float* bhh_f = (const float*)d_in[4];
    const float* Wih_b = (const float*)d_in[5];
    const float* Whh_b = (const float*)d_in[6];
    const float* bih_b = (const float*)d_in[7];
    const float* bhh_b = (const float*)d_in[8];
    float* out = (float*)d_out;

    static bool attr_set = false;
    if (!attr_set) {
        cudaFuncSetAttribute(lstm_scan_kernel,
                             cudaFuncAttributeMaxDynamicSharedMemorySize,
                             SMEM_WORDS * (int)sizeof(uint32_t));
        attr_set = true;
    }

    reset_cnt_kernel<<<1, 64>>>();
    cvt_kernel<<<2560, 256>>>(x, Wih_f, Wih_b);
    dim3 ggrid(16, 128, 2);
    gemm_xg_tc_kernel<<<ggrid, 256>>>(bih_f, bhh_f, bih_b, bhh_b);
    lstm_scan_kernel<<<NBLK, 512, SMEM_WORDS * sizeof(uint32_t)>>>(Whh_f, Whh_b, out);
}

// round 10
// speedup vs baseline: 4.1607x; 1.0560x over previous
#include <cuda_runtime.h>
#include <cuda_fp16.h>
#include <cstdint>

#define HID 512
#define BAT 32
#define TLEN 512
#define G4 2048
#define NBLK 128
#define NBLK_DIR 64
#define HP 40    // scan ht2s row pitch (uint32): conflict-free
#define RP2 36   // scan red row pitch (floats): finalize banks bijective
#define GP 20    // gemm smem row pitch (uint32): LDSM rows + STS conflict-free

#define X_WORDS (16384 * 256)
#define W_WORDS (2048 * 256)

// ----------------------------------------------------------------------------
// Scratch (static __device__ — no allocations allowed)
// ----------------------------------------------------------------------------
__device__ float    g_xg[2][TLEN][BAT][G4];    // xg[dir][t][b][gate]
__device__ uint32_t g_h2[2][2][256][32];       // [parity][dir][kp][b] packed half2
__device__ unsigned g_cnt[2][32];              // [dir][0] monotonic arrival counter
__device__ uint32_t g_xh2[X_WORDS];            // x as half2 k-pairs [m][kp], m=b*512+t
__device__ uint32_t g_wh2[2][W_WORDS];         // Wih as half2 k-pairs [n][kp]

// ----------------------------------------------------------------------------
// helpers
// ----------------------------------------------------------------------------
__device__ __forceinline__ float fex2(float x)
{ float y; asm("ex2.approx.f32 %0, %1;" : "=f"(y) : "f"(x)); return y; }
__device__ __forceinline__ float frcp(float x)
{ float y; asm("rcp.approx.f32 %0, %1;" : "=f"(y) : "f"(x)); return y; }

__device__ __forceinline__ float fsigmoid(float x)
{ return frcp(1.f + fex2(-1.4426950408889634f * x)); }
__device__ __forceinline__ float ftanh(float x)
{
    float ax = fabsf(x);
    float e = fex2(-2.8853900817779268f * ax);
    float t = 1.f - 2.f * e * frcp(1.f + e);
    return copysignf(t, x);
}

__device__ __forceinline__ void red_add_release(unsigned* p)
{ asm volatile("red.release.gpu.global.add.u32 [%0], 1;" :: "l"(p) : "memory"); }
__device__ __forceinline__ unsigned ld_acquire(const unsigned* p)
{ unsigned v; asm volatile("ld.acquire.gpu.global.u32 %0, [%1];" : "=r"(v) : "l"(p) : "memory"); return v; }

__device__ __forceinline__ uint32_t pack_h2(float a, float b)
{
    __half2 h = __floats2half2_rn(a, b);
    return *(uint32_t*)&h;
}

__device__ __forceinline__ void mma16816(float& d0, float& d1, float& d2, float& d3,
                                         uint32_t a0, uint32_t a1, uint32_t a2, uint32_t a3,
                                         uint32_t b0, uint32_t b1)
{
    asm("mma.sync.aligned.m16n8k16.row.col.f32.f16.f16.f32 "
        "{%0,%1,%2,%3}, {%4,%5,%6,%7}, {%8,%9}, {%0,%1,%2,%3};"
        : "+f"(d0), "+f"(d1), "+f"(d2), "+f"(d3)
        : "r"(a0), "r"(a1), "r"(a2), "r"(a3), "r"(b0), "r"(b1));
}

__device__ __forceinline__ void ldsm_x4(uint32_t& r0, uint32_t& r1,
                                        uint32_t& r2, uint32_t& r3, uint32_t addr)
{
    asm volatile("ldmatrix.sync.aligned.m8n8.x4.shared.b16 {%0,%1,%2,%3}, [%4];"
                 : "=r"(r0), "=r"(r1), "=r"(r2), "=r"(r3) : "r"(addr));
}

// ----------------------------------------------------------------------------
// Kernel 0a: zero arrival counters
// ----------------------------------------------------------------------------
__global__ void reset_cnt_kernel()
{
    ((unsigned*)g_cnt)[threadIdx.x] = 0u;
}

// ----------------------------------------------------------------------------
// Kernel 0b: convert x / Wih_f / Wih_b to half2 k-pair layout.
// ----------------------------------------------------------------------------
__global__ void __launch_bounds__(256) cvt_kernel(
    const float* __restrict__ x,
    const float* __restrict__ Wf,
    const float* __restrict__ Wb)
{
    size_t w = ((size_t)blockIdx.x * 256 + threadIdx.x) * 8;
    const float* src;
    uint32_t* dst;
    if (w < X_WORDS)                     { src = x  + 2 * w;               dst = g_xh2 + w; }
    else if (w < X_WORDS + W_WORDS)      { src = Wf + 2 * (w - X_WORDS);   dst = g_wh2[0] + (w - X_WORDS); }
    else                                 { src = Wb + 2 * (w - X_WORDS - W_WORDS);
                                           dst = g_wh2[1] + (w - X_WORDS - W_WORDS); }
    const float4* s = (const float4*)src;
    #pragma unroll
    for (int i = 0; i < 4; i++) {
        float4 v = s[i];
        dst[2 * i]     = pack_h2(v.x, v.y);
        dst[2 * i + 1] = pack_h2(v.z, v.w);
    }
}

// ----------------------------------------------------------------------------
// Kernel 1: tensor-core input GEMM with ldmatrix fragment loads.
// Grid (16 n-tiles, 128 m-tiles, 2 dirs); 8 warps (4m x 2n), warp tile 32x64.
// K chunks of 32 (16 kp words), double-buffered smem, pitch GP=20 (LDSM/STS
// bank-verified). Per warp per k16: 2 LDSM.x4 (A) + 4 LDSM.x4 (B) + 16 HMMA.
// ----------------------------------------------------------------------------
__global__ void __launch_bounds__(256) gemm_xg_tc_kernel(
    const float* __restrict__ bihf, const float* __restrict__ bhhf,
    const float* __restrict__ bihb, const float* __restrict__ bhhb)
{
    __shared__ uint32_t smg[2][2][128 * GP];

    const int dir = blockIdx.z;
    const int n0 = blockIdx.x * 128;
    const int m0 = blockIdx.y * 128;
    const uint32_t* __restrict__ A = g_xh2 + (size_t)m0 * 256;
    const uint32_t* __restrict__ B = g_wh2[dir] + (size_t)n0 * 256;
    const float* __restrict__ bih = dir ? bihb : bihf;
    const float* __restrict__ bhh = dir ? bhhb : bhhf;

    const int tid = threadIdx.x;
    const int warp = tid >> 5, lane = tid & 31;
    const int g = lane >> 2, c = lane & 3;
    const int wm = warp & 3;            // rows wm*32 .. +31
    const int wn = warp >> 2;           // cols wn*64 .. +63
    const int lrow  = tid & 127;        // load row
    const int lhalf = tid >> 7;         // load k-half (8 words)

    // ldmatrix lane addressing components
    const int qq = lane >> 3;           // matrix index 0..3
    const int rr = lane & 7;            // row within matrix
    const uint32_t smbase = (uint32_t)__cvta_generic_to_shared(&smg[0][0][0]);
    const uint32_t BUFSZ = 2u * 128u * GP * 4u;         // bytes per double-buffer slot
    // A: row = wm*32 + mt*16 + (qq&1)*8 + rr, word = ks*8 + (qq>>1)*4
    const uint32_t a_off0 = ((wm * 32 + (qq & 1) * 8 + rr) * GP + (qq >> 1) * 4) * 4u;
    // B: row = wn*64 + p*16 + (qq>>1)*8 + rr, word = ks*8 + (qq&1)*4
    const uint32_t b_off0 = (128u * GP + ((wn * 64 + (qq >> 1) * 8 + rr) * GP + (qq & 1) * 4)) * 4u;

    float acc[2][8][4];
    #pragma unroll
    for (int mt = 0; mt < 2; mt++)
        #pragma unroll
        for (int nt = 0; nt < 8; nt++)
            #pragma unroll
            for (int q = 0; q < 4; q++) acc[mt][nt][q] = 0.f;

    uint4 pa0, pa1, pb0, pb1;
    {
        const uint4* pa = (const uint4*)(A + (size_t)lrow * 256 + lhalf * 8);
        pa0 = pa[0]; pa1 = pa[1];
        const uint4* pb = (const uint4*)(B + (size_t)lrow * 256 + lhalf * 8);
        pb0 = pb[0]; pb1 = pb[1];
    }
    {
        uint4* as = (uint4*)&smg[0][0][lrow * GP + lhalf * 8];
        as[0] = pa0; as[1] = pa1;
        uint4* bs = (uint4*)&smg[0][1][lrow * GP + lhalf * 8];
        bs[0] = pb0; bs[1] = pb1;
    }
    __syncthreads();

    for (int kc = 0; kc < 16; kc++) {
        if (kc < 15) {
            const uint4* pa = (const uint4*)(A + (size_t)lrow * 256 + (kc + 1) * 16 + lhalf * 8);
            pa0 = pa[0]; pa1 = pa[1];
            const uint4* pb = (const uint4*)(B + (size_t)lrow * 256 + (kc + 1) * 16 + lhalf * 8);
            pb0 = pb[0]; pb1 = pb[1];
        }
        const uint32_t bufb = smbase + (kc & 1) * BUFSZ;
        #pragma unroll
        for (int ks = 0; ks < 2; ks++) {
            const uint32_t ksb = bufb + ks * 8 * 4u;
            uint32_t af[2][4];
            #pragma unroll
            for (int mt = 0; mt < 2; mt++)
                ldsm_x4(af[mt][0], af[mt][1], af[mt][2], af[mt][3],
                        ksb + a_off0 + mt * (16 * GP * 4u));
            uint32_t bf[4][4];
            #pragma unroll
            for (int p = 0; p < 4; p++)
                ldsm_x4(bf[p][0], bf[p][1], bf[p][2], bf[p][3],
                        ksb + b_off0 + p * (16 * GP * 4u));
            #pragma unroll
            for (int nt = 0; nt < 8; nt++) {
                uint32_t b0 = bf[nt >> 1][(nt & 1) * 2 + 0];
                uint32_t b1 = bf[nt >> 1][(nt & 1) * 2 + 1];
                #pragma unroll
                for (int mt = 0; mt < 2; mt++)
                    mma16816(acc[mt][nt][0], acc[mt][nt][1], acc[mt][nt][2], acc[mt][nt][3],
                             af[mt][0], af[mt][1], af[mt][2], af[mt][3], b0, b1);
            }
        }
        if (kc < 15) {
            __syncthreads();   // done reading buffer (kc+1)&1 from 2 chunks ago
            uint4* asw = (uint4*)&smg[(kc + 1) & 1][0][lrow * GP + lhalf * 8];
            asw[0] = pa0; asw[1] = pa1;
            uint4* bsw = (uint4*)&smg[(kc + 1) & 1][1][lrow * GP + lhalf * 8];
            bsw[0] = pb0; bsw[1] = pb1;
            __syncthreads();
        }
    }

    // epilogue: bias + fp32 store to g_xg
    float bias0[8], bias1[8];
    #pragma unroll
    for (int nt = 0; nt < 8; nt++) {
        int n = n0 + wn * 64 + nt * 8 + 2 * c;
        bias0[nt] = bih[n] + bhh[n];
        bias1[nt] = bih[n + 1] + bhh[n + 1];
    }
    #pragma unroll
    for (int mt = 0; mt < 2; mt++) {
        #pragma unroll
        for (int rw = 0; rw < 2; rw++) {
            int m = m0 + wm * 32 + mt * 16 + g + rw * 8;
            int t = m & 511;
            int b = m >> 9;
            float* o = &g_xg[dir][t][b][n0 + wn * 64];
            #pragma unroll
            for (int nt = 0; nt < 8; nt++) {
                float2 v = make_float2(acc[mt][nt][rw * 2 + 0] + bias0[nt],
                                       acc[mt][nt][rw * 2 + 1] + bias1[nt]);
                *(float2*)&o[nt * 8 + 2 * c] = v;
            }
        }
    }
}

// ----------------------------------------------------------------------------
// Kernel 2: persistent scan — tensor-pipe recurrent matmul (R8/R9 structure,
// mma dependency chain split into two independent 8-deep accumulators).
// ----------------------------------------------------------------------------
#define SMEM_WORDS (256 * HP + 2 * 32 * RP2)   // 12544 words = 50176 B

__global__ void __launch_bounds__(512, 1) lstm_scan_kernel(
    const float* __restrict__ Whh_f,
    const float* __restrict__ Whh_b,
    float* __restrict__ out)
{
    extern __shared__ uint32_t smu[];
    uint32_t* ht2s = smu;                         // [256][HP]
    float*    red  = (float*)(smu + 256 * HP);    // [2][32][RP2]

    const int tid = threadIdx.x;
    const int dir = blockIdx.x >> 6;
    const int j0  = (blockIdx.x & 63) * 8;
    const float* __restrict__ Whh = dir ? Whh_b : Whh_f;

    const int warp = tid >> 5;
    const int lane = tid & 31;
    const int wm = warp & 1;
    const int kh = (warp >> 1) & 1;
    const int wn = warp >> 2;
    const int g  = lane >> 2;
    const int c  = lane & 3;

    uint32_t afrag[16][4];
    {
        int r0 = wm * 16 + g;
        const float* rowA = Whh + (size_t)((r0 >> 3) * 512 + j0 + (r0 & 7)) * 512;
        const float* rowB = Whh + (size_t)((((r0 + 8) >> 3)) * 512 + j0 + ((r0 + 8) & 7)) * 512;
        #pragma unroll
        for (int kt = 0; kt < 16; kt++) {
            int kb = kh * 256 + kt * 16 + 2 * c;
            afrag[kt][0] = pack_h2(rowA[kb],     rowA[kb + 1]);
            afrag[kt][1] = pack_h2(rowB[kb],     rowB[kb + 1]);
            afrag[kt][2] = pack_h2(rowA[kb + 8], rowA[kb + 9]);
            afrag[kt][3] = pack_h2(rowB[kb + 8], rowB[kb + 9]);
        }
    }

    for (int i = tid; i < 256 * HP; i += 512) ht2s[i] = 0u;

    const int fb = tid >> 3;
    const int fj = tid & 7;
    float c_state = 0.f;

    unsigned* cnt = &g_cnt[dir][0];
    const float* xg_base = &g_xg[dir][0][fb & 31][j0 + fj];
    float* out_base = out + (size_t)(fb & 31) * (TLEN * 1024) + dir * 512 + j0 + fj;
    uint32_t* h2_base0 = &g_h2[0][dir][(j0 + fj) >> 1][fb & 31];
    uint32_t* h2_base1 = &g_h2[1][dir][(j0 + fj) >> 1][fb & 31];

    __syncthreads();

    for (int s = 0; s < 512; s++) {
        const int t = dir ? (511 - s) : s;

        float xi = 0.f, xf = 0.f, xgv = 0.f, xo = 0.f;
        if (tid < 256) {
            const float* xgp = xg_base + (size_t)t * (BAT * G4);
            xi  = __ldcs(xgp);
            xf  = __ldcs(xgp + 512);
            xgv = __ldcs(xgp + 1024);
            xo  = __ldcs(xgp + 1536);
        }

        // two independent accumulator chains (kt even / odd)
        float d0 = 0.f, d1 = 0.f, d2 = 0.f, d3 = 0.f;
        float e0 = 0.f, e1 = 0.f, e2 = 0.f, e3 = 0.f;
        #pragma unroll
        for (int kt = 0; kt < 16; kt += 2) {
            int kp0 = kh * 128 + kt * 8;
            uint32_t b0 = ht2s[(kp0 + c) * HP + wn * 8 + g];
            uint32_t b1 = ht2s[(kp0 + 4 + c) * HP + wn * 8 + g];
            mma16816(d0, d1, d2, d3,
                     afrag[kt][0], afrag[kt][1], afrag[kt][2], afrag[kt][3], b0, b1);
            int kp1 = kp0 + 8;
            uint32_t b2 = ht2s[(kp1 + c) * HP + wn * 8 + g];
            uint32_t b3 = ht2s[(kp1 + 4 + c) * HP + wn * 8 + g];
            mma16816(e0, e1, e2, e3,
                     afrag[kt + 1][0], afrag[kt + 1][1], afrag[kt + 1][2], afrag[kt + 1][3], b2, b3);
        }

        {
            float* rp = red + kh * (32 * RP2) + (wm * 16 + g) * RP2 + wn * 8 + 2 * c;
            *(float2*)rp             = make_float2(d0 + e0, d1 + e1);
            *(float2*)(rp + 8 * RP2) = make_float2(d2 + e2, d3 + e3);
        }
        __syncthreads();

        float hval = 0.f;
        if (tid < 256) {
            float dd[4];
            #pragma unroll
            for (int gate = 0; gate < 4; gate++) {
                int off = (gate * 8 + fj) * RP2 + fb;
                dd[gate] = red[off] + red[32 * RP2 + off];
            }
            float ig = fsigmoid(xi  + dd[0]);
            float fg = fsigmoid(xf  + dd[1]);
            float gg = ftanh(xgv + dd[2]);
            float og = fsigmoid(xo  + dd[3]);
            c_state = fg * c_state + ig * gg;
            hval = og * ftanh(c_state);

            if (s < 511) {
                float hpart = __shfl_xor_sync(0xffffffffu, hval, 1);
                if ((fj & 1) == 0) {
                    uint32_t v = pack_h2(hval, hpart);
                    *((s & 1) ? h2_base1 : h2_base0) = v;
                }
            }
        }

        if (s < 511) {
            __syncthreads();
            if (tid == 0) red_add_release(cnt);

            if (tid < 256)
                out_base[(size_t)t * 1024] = hval;

            if (tid == 0) {
                const unsigned tgt = (unsigned)((s + 1) * NBLK_DIR);
                while ((int)(ld_acquire(cnt) - tgt) < 0) { }
            }
            __syncthreads();

            const uint32_t* src = &g_h2[s & 1][dir][0][0];
            #pragma unroll
            for (int i = 0; i < 16; i++) {
                int kp = warp * 16 + i;
                uint32_t v = __ldcg(&src[kp * 32 + lane]);
                ht2s[kp * HP + lane] = v;
            }
            __syncthreads();
        } else {
            if (tid < 256)
                out_base[(size_t)t * 1024] = hval;
        }
    }
}

// ----------------------------------------------------------------------------
// Launch
// ----------------------------------------------------------------------------
extern "C" void kernel_launch(void* const* d_in, const int* in_sizes, int n_in,
                              void* d_out, int out_size)
{
    (void)in_sizes; (void)n_in; (void)out_size;
    const float* x     = (const float*)d_in[0];
    const float* Wih_f = (const float*)d_in[1];
    const float* Whh_f = (const float*)d_in[2];
    const float* bih_f = (const float*)d_in[3];
    const float* bhh_f = (const float*)d_in[4];
    const float* Wih_b = (const float*)d_in[5];
    const float* Whh_b = (const float*)d_in[6];
    const float* bih_b = (const float*)d_in[7];
    const float* bhh_b = (const float*)d_in[8];
    float* out = (float*)d_out;

    static bool attr_set = false;
    if (!attr_set) {
        cudaFuncSetAttribute(lstm_scan_kernel,
                             cudaFuncAttributeMaxDynamicSharedMemorySize,
                             SMEM_WORDS * (int)sizeof(uint32_t));
        attr_set = true;
    }

    reset_cnt_kernel<<<1, 64>>>();
    cvt_kernel<<<2560, 256>>>(x, Wih_f, Wih_b);
    dim3 ggrid(16, 128, 2);
    gemm_xg_tc_kernel<<<ggrid, 256>>>(bih_f, bhh_f, bih_b, bhh_b);
    lstm_scan_kernel<<<NBLK, 512, SMEM_WORDS * sizeof(uint32_t)>>>(Whh_f, Whh_b, out);
}